// round 13
// baseline (speedup 1.0000x reference)
#include <cuda_runtime.h>
#include <cuda_fp16.h>
#include <math.h>
#include <stdint.h>

// Problem constants
constexpr int D   = 768;
constexpr int S   = 128;
constexpr int BSN = 4096;    // B*S
constexpr int NN  = 12288;   // 3*B*S
constexpr int H3  = 2304;    // 3*D

// Scratch (device globals — allocation-free rule)
__device__ float  g_xw[S * D];            // raw xw for first 128 rows only
__device__ float  g_z[NN * D];            // MLP pre-LN output
__device__ __half g_ghh[(size_t)NN * H3]; // GRU gh (fp16)
__device__ float  g_feats32[S * D];
__device__ __half g_featsh[NN * D];       // feats fp16; reused as y fp16
__device__ __half g_xh[NN * D];           // x state fp16; reused as MLP hidden
__device__ __half g_whh_h[H3 * D];
__device__ __half g_wtg_h[D * D];
__device__ __half g_wt1_h[3 * D * D];
__device__ __half g_wt2_h[3 * D * D];
__device__ float  g_sim[S * S];
__device__ float  g_nrm[S];
__device__ float  g_dinv[S];
__device__ float  g_deginv[S];
__device__ float  g_svec[D];
__device__ float  g_mvec[D];
__device__ float  g_gi[H3];

// ============================ mma.sync helpers =============================
__device__ __forceinline__ uint32_t smem_u32(const void* p) {
    uint32_t a;
    asm("{ .reg .u64 t; cvta.to.shared.u64 t, %1; cvt.u32.u64 %0, t; }"
        : "=r"(a) : "l"(p));
    return a;
}
__device__ __forceinline__ void ldm_x4(uint32_t& r0, uint32_t& r1,
                                       uint32_t& r2, uint32_t& r3, uint32_t addr) {
    asm volatile("ldmatrix.sync.aligned.m8n8.x4.shared.b16 {%0,%1,%2,%3}, [%4];"
                 : "=r"(r0), "=r"(r1), "=r"(r2), "=r"(r3) : "r"(addr));
}
__device__ __forceinline__ void mma_f16(float* c, const uint32_t* a,
                                        const uint32_t* b) {
    asm volatile(
        "mma.sync.aligned.m16n8k16.row.col.f32.f16.f16.f32 "
        "{%0,%1,%2,%3}, {%4,%5,%6,%7}, {%8,%9}, {%0,%1,%2,%3};"
        : "+f"(c[0]), "+f"(c[1]), "+f"(c[2]), "+f"(c[3])
        : "r"(a[0]), "r"(a[1]), "r"(a[2]), "r"(a[3]), "r"(b[0]), "r"(b[1]));
}
__device__ __forceinline__ float sigm(float v) { return 1.f / (1.f + expf(-v)); }
#define CP16(dst, src) \
    asm volatile("cp.async.cg.shared.global [%0], [%1], 16;" :: "r"(dst), "l"(src))
#define CP_COMMIT() asm volatile("cp.async.commit_group;" ::: "memory")
#define CP_WAIT1()  asm volatile("cp.async.wait_group 1;" ::: "memory")

// ===========================================================================
// fp16 mma.sync GEMM: C[m,n] = sum_k A[m,k]*B[n,k]
// Block 128x256, BK=64 (4 k16 steps/iter, 12 iterations -> half the syncs),
// 8 warps (2m x 4n), warp tile 64x64, 3-stage cp.async (wait_group 1).
// Rows padded to 144B (128B data + 16B): 16B-aligned, LDSM conflict-free.
// EPI: 0 none, 1 bias, 2 bias+relu. OUTH: fp16 out.
// GCN: bm==0 tile writes raw fp32 to Caux; others bias+relu fp16 to Cv.
// ===========================================================================
constexpr int BM = 128, BN = 256, BK = 64;
constexpr int ROWB2 = 144;                            // bytes per SMEM row
constexpr uint32_t A_BYTES = BM * ROWB2;              // 18432
constexpr uint32_t STAGE_BYTES = (BM + BN) * ROWB2;   // 55296
constexpr uint32_t SMEM_BYTES = 3 * STAGE_BYTES;      // 165888

template <int EPI, bool OUTH, bool GCN>
__global__ void __launch_bounds__(256, 1) h_gemm(
    const __half* __restrict__ A,
    const __half* __restrict__ B0, const __half* __restrict__ B1,
    const __half* __restrict__ B2,
    const float* __restrict__ bias0, const float* __restrict__ bias1,
    const float* __restrict__ bias2,
    void* __restrict__ Cv, float* __restrict__ Caux,
    int M, int N, int K, int rowSeg)
{
    extern __shared__ char smem[];
    const int bn = blockIdx.x * BN;
    const int bm = blockIdx.y * BM;
    const int seg = bm / rowSeg;
    const __half* Bp  = (seg == 0) ? B0 : ((seg == 1) ? B1 : B2);
    const float* bias = (seg == 0) ? bias0 : ((seg == 1) ? bias1 : bias2);

    const int tid  = threadIdx.x;
    const int lane = tid & 31;
    const int wid  = tid >> 5;
    const int wm   = (wid >> 2) * 64;
    const int wn   = (wid & 3) * 64;

    const uint32_t sS = smem_u32(smem);

    // Loaders: A 128 rows x 128B (2 threads/row, 64B each);
    //          B 256 rows x 128B (1 thread/row, 128B each)
    const int alr = tid >> 1;
    const int ah  = (tid & 1) * 32;            // half offset within row (64B)
    const __half* Agl = A  + (size_t)(bm + alr) * K + ah;
    const __half* Bgl = Bp + (size_t)(bn + tid) * K;
    const uint32_t aDst = (uint32_t)alr * ROWB2 + ah * 2;
    const uint32_t bDst = A_BYTES + (uint32_t)tid * ROWB2;

#define LOAD_STAGE(s, kb) do { \
    const int _k0 = (kb) * BK; \
    const uint32_t _base = sS + (uint32_t)(s) * STAGE_BYTES; \
    const __half* _a = Agl + _k0; \
    CP16(_base + aDst,      _a);      CP16(_base + aDst + 16, _a + 8); \
    CP16(_base + aDst + 32, _a + 16); CP16(_base + aDst + 48, _a + 24); \
    const __half* _b = Bgl + _k0; \
    CP16(_base + bDst,       _b);      CP16(_base + bDst + 16,  _b + 8); \
    CP16(_base + bDst + 32,  _b + 16); CP16(_base + bDst + 48,  _b + 24); \
    CP16(_base + bDst + 64,  _b + 32); CP16(_base + bDst + 80,  _b + 40); \
    CP16(_base + bDst + 96,  _b + 48); CP16(_base + bDst + 112, _b + 56); \
} while (0)

    float c[4][8][4];
#pragma unroll
    for (int i = 0; i < 4; i++)
#pragma unroll
        for (int j = 0; j < 8; j++)
#pragma unroll
            for (int q = 0; q < 4; q++) c[i][j][q] = 0.f;

    LOAD_STAGE(0, 0); CP_COMMIT();
    LOAD_STAGE(1, 1); CP_COMMIT();

    const uint32_t aOff = (uint32_t)(wm + (lane & 15)) * ROWB2 + (lane >> 4) * 16;
    const uint32_t bOff = (uint32_t)(wn + (lane & 7) + ((lane >> 4) << 3)) * ROWB2
                          + ((lane >> 3) & 1) * 16;

    const int NS = K / BK;   // 12
    for (int ks = 0; ks < NS; ks++) {
        CP_WAIT1();
        __syncthreads();
        if (ks + 2 < NS) {
            LOAD_STAGE((ks + 2) % 3, ks + 2);
            CP_COMMIT();
        }
        const uint32_t aB = sS + (uint32_t)(ks % 3) * STAGE_BYTES;
        const uint32_t bB = aB + A_BYTES;
#pragma unroll
        for (int kh = 0; kh < 4; kh++) {
            uint32_t af[4][4], bf[8][2];
#pragma unroll
            for (int mt = 0; mt < 4; mt++)
                ldm_x4(af[mt][0], af[mt][1], af[mt][2], af[mt][3],
                       aB + aOff + kh * 32 + (uint32_t)mt * (16 * ROWB2));
#pragma unroll
            for (int jp = 0; jp < 4; jp++) {
                uint32_t r0, r1, r2, r3;
                ldm_x4(r0, r1, r2, r3,
                       bB + bOff + kh * 32 + (uint32_t)jp * (16 * ROWB2));
                bf[2 * jp][0] = r0;     bf[2 * jp][1] = r1;
                bf[2 * jp + 1][0] = r2; bf[2 * jp + 1][1] = r3;
            }
#pragma unroll
            for (int mt = 0; mt < 4; mt++)
#pragma unroll
                for (int nt = 0; nt < 8; nt++)
                    mma_f16(c[mt][nt], af[mt], bf[nt]);
        }
    }

    const int er = lane >> 2;
    const int ec = (lane & 3) * 2;
    const bool rawTile = GCN && (bm == 0);
#pragma unroll
    for (int mt = 0; mt < 4; mt++) {
        const int m = bm + wm + mt * 16 + er;
#pragma unroll
        for (int nt = 0; nt < 8; nt++) {
            const int n = bn + wn + nt * 8 + ec;
            float2 v0 = make_float2(c[mt][nt][0], c[mt][nt][1]);
            float2 v1 = make_float2(c[mt][nt][2], c[mt][nt][3]);
            if (rawTile) {
                *(float2*)(Caux + (size_t)m * N + n)       = v0;
                *(float2*)(Caux + (size_t)(m + 8) * N + n) = v1;
                continue;
            }
            if (EPI >= 1) {
                float b0 = bias[n], b1 = bias[n + 1];
                v0.x += b0; v0.y += b1;
                v1.x += b0; v1.y += b1;
            }
            if (EPI == 2) {
                v0.x = fmaxf(v0.x, 0.f); v0.y = fmaxf(v0.y, 0.f);
                v1.x = fmaxf(v1.x, 0.f); v1.y = fmaxf(v1.y, 0.f);
            }
            if (OUTH) {
                __half* Ch = (__half*)Cv;
                *(__half2*)(Ch + (size_t)m * N + n)       = __floats2half2_rn(v0.x, v0.y);
                *(__half2*)(Ch + (size_t)(m + 8) * N + n) = __floats2half2_rn(v1.x, v1.y);
            } else {
                float* Cf = (float*)Cv;
                *(float2*)(Cf + (size_t)m * N + n)       = v0;
                *(float2*)(Cf + (size_t)(m + 8) * N + n) = v1;
            }
        }
    }
#undef LOAD_STAGE
}

// ============================ small kernels ================================
__global__ void k_transpose_h(const float* __restrict__ src, __half* __restrict__ dst)
{
    __shared__ float t[32][33];
    int bx = blockIdx.x * 32, by = blockIdx.y * 32;
    int x = bx + threadIdx.x;
#pragma unroll
    for (int j = 0; j < 32; j += 8)
        t[threadIdx.y + j][threadIdx.x] = src[(size_t)(by + threadIdx.y + j) * D + x];
    __syncthreads();
    int ox = by + threadIdx.x;
#pragma unroll
    for (int j = 0; j < 32; j += 8)
        dst[(size_t)(bx + threadIdx.y + j) * D + ox] = __float2half(t[threadIdx.x][threadIdx.y + j]);
}

__global__ void k_cvt_h(const float* __restrict__ src, __half* __restrict__ dst)
{
    int i = blockIdx.x * 256 + threadIdx.x;
    dst[i] = __float2half(src[i]);
}

__global__ void k_gather(const float* __restrict__ a, const float* __restrict__ b,
                         const float* __restrict__ c)
{
    int o = blockIdx.x * 256 + threadIdx.x;
    int n = o / D;
    int d = o - n * D;
    int t = d % 3;
    const float* s = (t == 0) ? a : ((t == 1) ? b : c);
    float v = s[n * (D / 3) + d / 3];
    g_featsh[o] = __float2half(v);
    if (o < S * D) g_feats32[o] = v;
}

__global__ void k_norm()
{
    int i = blockIdx.x;
    float s = 0.f;
    for (int k = threadIdx.x; k < D; k += 256) {
        float v = g_feats32[i * D + k];
        s = fmaf(v, v, s);
    }
    __shared__ float sh[256];
    sh[threadIdx.x] = s; __syncthreads();
    for (int t = 128; t > 0; t >>= 1) {
        if (threadIdx.x < t) sh[threadIdx.x] += sh[threadIdx.x + t];
        __syncthreads();
    }
    if (threadIdx.x == 0) g_nrm[i] = fmaxf(sqrtf(sh[0]), 1e-8f);
}

__global__ void k_sim()
{
    int i = blockIdx.x;
    __shared__ float fi[D];
    for (int k = threadIdx.x; k < D; k += 256) fi[k] = g_feats32[i * D + k];
    __syncthreads();
    int warp = threadIdx.x >> 5, lane = threadIdx.x & 31;
    float ni = g_nrm[i];
    for (int jj = 0; jj < 16; jj++) {
        int j = warp * 16 + jj;
        float s = 0.f;
        for (int k = lane; k < D; k += 32) s = fmaf(fi[k], g_feats32[j * D + k], s);
        for (int o = 16; o > 0; o >>= 1) s += __shfl_down_sync(0xffffffffu, s, o);
        if (lane == 0) g_sim[i * S + j] = s / (ni * g_nrm[j]);
    }
}

__global__ void k_simnorm()
{
    __shared__ float smn[256], smx[256];
    int tid = threadIdx.x;
    float mn = 1e30f, mx = -1e30f;
    for (int e = tid; e < S * S; e += 256) {
        float v = g_sim[e];
        mn = fminf(mn, v); mx = fmaxf(mx, v);
    }
    smn[tid] = mn; smx[tid] = mx;
    __syncthreads();
    for (int t = 128; t > 0; t >>= 1) {
        if (tid < t) {
            smn[tid] = fminf(smn[tid], smn[tid + t]);
            smx[tid] = fmaxf(smx[tid], smx[tid + t]);
        }
        __syncthreads();
    }
    float lo = smn[0];
    float inv = 1.f / (smx[0] - smn[0]);
    __syncthreads();
    for (int e = tid; e < S * S; e += 256) g_sim[e] = (g_sim[e] - lo) * inv;
    __syncthreads();
    if (tid < S) {
        float dg = 1.f;
        for (int i = 0; i < S; i++) dg += g_sim[i * S + tid];
        g_dinv[tid]   = rsqrtf(dg);
        g_deginv[tid] = 1.f / dg;
    }
}

__global__ void k_gcn_first(const float* __restrict__ gcn_b)
{
    int c = blockIdx.x;
    int d = blockIdx.y * 128 + threadIdx.x;
    __shared__ float col[S];
    col[threadIdx.x] = g_dinv[threadIdx.x] * g_sim[threadIdx.x * S + c];
    __syncthreads();
    float acc = 0.f;
#pragma unroll 8
    for (int i = 0; i < S; i++) acc = fmaf(col[i], g_xw[i * D + d], acc);
    float v = g_dinv[c] * acc + g_xw[c * D + d] * g_deginv[c] + gcn_b[d];
    g_xh[c * D + d] = __float2half(fmaxf(v, 0.f));
}

__global__ void k_colsum()
{
    int d = blockIdx.x * 256 + threadIdx.x;
    float s = 0.f;
    for (int r = 0; r < S; r++) s += __half2float(g_xh[r * D + d]);
    g_svec[d] = s;
}

__global__ void k_mvec(const float* __restrict__ W)
{
    int d = blockIdx.x * 256 + threadIdx.x;
    float acc = 0.f;
    for (int k = 0; k < D; k++) acc = fmaf(g_svec[k], W[k * D + d], acc);
    g_mvec[d] = acc;
}

__global__ void k_gi(const float* __restrict__ wih, const float* __restrict__ bih)
{
    int warp = threadIdx.x >> 5, lane = threadIdx.x & 31;
    int o = blockIdx.x * 8 + warp;
    float s = 0.f;
    for (int k = lane; k < D; k += 32) s = fmaf(g_mvec[k], wih[o * D + k], s);
    for (int off = 16; off > 0; off >>= 1) s += __shfl_down_sync(0xffffffffu, s, off);
    if (lane == 0) g_gi[o] = s + bih[o];
}

template <bool LAST>
__global__ void k_gru(const float* __restrict__ bih, const float* __restrict__ hfeat)
{
    int p = blockIdx.x * 256 + threadIdx.x;   // pair index
    int o = p * 2;
    int n = o / D;
    int d = o - n * D;
    float gir0, gir1, giz0, giz1, gin0, gin1;
    if (n < S) {
        gir0 = g_gi[d];        gir1 = g_gi[d + 1];
        giz0 = g_gi[D + d];    giz1 = g_gi[D + d + 1];
        gin0 = g_gi[2*D + d];  gin1 = g_gi[2*D + d + 1];
    } else {
        gir0 = bih[d];         gir1 = bih[d + 1];
        giz0 = bih[D + d];     giz1 = bih[D + d + 1];
        gin0 = bih[2*D + d];   gin1 = bih[2*D + d + 1];
    }
    const size_t gb = (size_t)n * H3;
    float2 hr = __half22float2(*(const __half2*)(g_ghh + gb + d));
    float2 hz = __half22float2(*(const __half2*)(g_ghh + gb + D + d));
    float2 hn = __half22float2(*(const __half2*)(g_ghh + gb + 2*D + d));
    float2 h  = __half22float2(*(const __half2*)(g_xh + o));
    float r0 = sigm(gir0 + hr.x), r1 = sigm(gir1 + hr.y);
    float z0 = sigm(giz0 + hz.x), z1 = sigm(giz1 + hz.y);
    float n0 = tanhf(gin0 + r0 * hn.x), n1 = tanhf(gin1 + r1 * hn.y);
    float o0 = (1.f - z0) * n0 + z0 * h.x;
    float o1 = (1.f - z1) * n1 + z1 * h.y;
    if (LAST) {
        int hb = o % (BSN * D);
        float2 hf = *(const float2*)(hfeat + hb);
        *(__half2*)(g_featsh + o) =
            __floats2half2_rn(hf.x + fmaxf(o0, 0.f), hf.y + fmaxf(o1, 0.f));
    } else {
        *(__half2*)(g_xh + o) = __floats2half2_rn(o0, o1);
    }
}

__global__ void k_ln(const float* __restrict__ g1, const float* __restrict__ be1,
                     const float* __restrict__ g2, const float* __restrict__ be2,
                     const float* __restrict__ g3, const float* __restrict__ be3,
                     float* __restrict__ out)
{
    int r = blockIdx.x;
    int t = r / BSN;
    const float* gg = (t == 0) ? g1 : ((t == 1) ? g2 : g3);
    const float* bb = (t == 0) ? be1 : ((t == 1) ? be2 : be3);
    const float* z = g_z + (size_t)r * D;
    int tid = threadIdx.x;
    float v0 = z[tid], v1 = z[tid + 256], v2 = z[tid + 512];
    __shared__ float sh[256];
    sh[tid] = v0 + v1 + v2; __syncthreads();
    for (int s = 128; s > 0; s >>= 1) {
        if (tid < s) sh[tid] += sh[tid + s];
        __syncthreads();
    }
    float mu = sh[0] * (1.f / 768.f);
    __syncthreads();
    float d0 = v0 - mu, d1 = v1 - mu, d2 = v2 - mu;
    sh[tid] = d0 * d0 + d1 * d1 + d2 * d2; __syncthreads();
    for (int s = 128; s > 0; s >>= 1) {
        if (tid < s) sh[tid] += sh[tid + s];
        __syncthreads();
    }
    float rstd = rsqrtf(sh[0] * (1.f / 768.f) + 1e-5f);
    float* o = out + (size_t)r * D;
    o[tid]       = d0 * rstd * gg[tid]       + bb[tid];
    o[tid + 256] = d1 * rstd * gg[tid + 256] + bb[tid + 256];
    o[tid + 512] = d2 * rstd * gg[tid + 512] + bb[tid + 512];
}

// ---------------------------------------------------------------------------
extern "C" void kernel_launch(void* const* d_in, const int* in_sizes, int n_in,
                              void* d_out, int out_size)
{
    const float* h_feature = (const float*)d_in[0];
    const float* h_con     = (const float*)d_in[1];
    const float* h_dep     = (const float*)d_in[2];
    const float* h_sem     = (const float*)d_in[3];
    const float* gcn_W     = (const float*)d_in[4];
    const float* gcn_b     = (const float*)d_in[5];
    const float* ggc_W     = (const float*)d_in[6];
    const float* gru_wih   = (const float*)d_in[7];
    const float* gru_whh   = (const float*)d_in[8];
    const float* gru_bih   = (const float*)d_in[9];
    const float* gru_bhh   = (const float*)d_in[10];
    const float* rW1[3]   = {(const float*)d_in[11], (const float*)d_in[17], (const float*)d_in[23]};
    const float* rb1[3]   = {(const float*)d_in[12], (const float*)d_in[18], (const float*)d_in[24]};
    const float* rW2[3]   = {(const float*)d_in[13], (const float*)d_in[19], (const float*)d_in[25]};
    const float* rb2[3]   = {(const float*)d_in[14], (const float*)d_in[20], (const float*)d_in[26]};
    const float* rg[3]    = {(const float*)d_in[15], (const float*)d_in[21], (const float*)d_in[27]};
    const float* rbeta[3] = {(const float*)d_in[16], (const float*)d_in[22], (const float*)d_in[28]};
    float* out = (float*)d_out;

    float *xw, *zbuf;
    __half *ghh, *featsh, *xh, *whh_h, *wtg_h, *wt1_h, *wt2_h;
    cudaGetSymbolAddress((void**)&xw,     g_xw);
    cudaGetSymbolAddress((void**)&zbuf,   g_z);
    cudaGetSymbolAddress((void**)&ghh,    g_ghh);
    cudaGetSymbolAddress((void**)&featsh, g_featsh);
    cudaGetSymbolAddress((void**)&xh,     g_xh);
    cudaGetSymbolAddress((void**)&whh_h,  g_whh_h);
    cudaGetSymbolAddress((void**)&wtg_h,  g_wtg_h);
    cudaGetSymbolAddress((void**)&wt1_h,  g_wt1_h);
    cudaGetSymbolAddress((void**)&wt2_h,  g_wt2_h);

    // One-time stream/event setup (runs during the un-captured correctness call)
    static cudaStream_t s1 = nullptr, s2 = nullptr;
    static cudaEvent_t evRoot, evW1, evW2, evG, evSim, evX[2], evGi[2];
    if (!s1) {
        cudaStreamCreateWithFlags(&s1, cudaStreamNonBlocking);
        cudaStreamCreateWithFlags(&s2, cudaStreamNonBlocking);
        cudaEventCreateWithFlags(&evRoot, cudaEventDisableTiming);
        cudaEventCreateWithFlags(&evW1,   cudaEventDisableTiming);
        cudaEventCreateWithFlags(&evW2,   cudaEventDisableTiming);
        cudaEventCreateWithFlags(&evG,    cudaEventDisableTiming);
        cudaEventCreateWithFlags(&evSim,  cudaEventDisableTiming);
        for (int i = 0; i < 2; i++) {
            cudaEventCreateWithFlags(&evX[i],  cudaEventDisableTiming);
            cudaEventCreateWithFlags(&evGi[i], cudaEventDisableTiming);
        }
        cudaFuncSetAttribute((const void*)h_gemm<2, true, true>,
                             cudaFuncAttributeMaxDynamicSharedMemorySize, SMEM_BYTES);
        cudaFuncSetAttribute((const void*)h_gemm<1, true, false>,
                             cudaFuncAttributeMaxDynamicSharedMemorySize, SMEM_BYTES);
        cudaFuncSetAttribute((const void*)h_gemm<2, true, false>,
                             cudaFuncAttributeMaxDynamicSharedMemorySize, SMEM_BYTES);
        cudaFuncSetAttribute((const void*)h_gemm<1, false, false>,
                             cudaFuncAttributeMaxDynamicSharedMemorySize, SMEM_BYTES);
    }

    dim3 tb(32, 8);
    dim3 tg(D / 32, D / 32);

    // ---- fork weight prep onto s1 (no data deps)
    cudaEventRecord(evRoot, 0);
    cudaStreamWaitEvent(s1, evRoot, 0);
    k_transpose_h<<<tg, tb, 0, s1>>>(gcn_W, wtg_h);
    cudaEventRecord(evW1, s1);   // wtg ready (needed by GEMM1)
    for (int t = 0; t < 3; t++) {
        k_transpose_h<<<tg, tb, 0, s1>>>(rW1[t], wt1_h + (size_t)t * D * D);
        k_transpose_h<<<tg, tb, 0, s1>>>(rW2[t], wt2_h + (size_t)t * D * D);
    }
    k_cvt_h<<<H3 * D / 256, 256, 0, s1>>>(gru_whh, whh_h);
    cudaEventRecord(evW2, s1);   // all other weights ready

    // ---- main stream: gather, then fork the sim chain onto s2
    k_gather<<<NN * D / 256, 256>>>(h_con, h_dep, h_sem);
    cudaEventRecord(evG, 0);
    cudaStreamWaitEvent(s2, evG, 0);
    k_norm<<<S, 256, 0, s2>>>();
    k_sim<<<S, 256, 0, s2>>>();
    k_simnorm<<<1, 256, 0, s2>>>();
    cudaEventRecord(evSim, s2);

    // ---- GEMM1 (xw) overlaps with the sim chain
    cudaStreamWaitEvent(0, evW1, 0);
    h_gemm<2, true, true><<<dim3(D / BN, NN / BM), 256, SMEM_BYTES>>>(
        featsh, wtg_h, wtg_h, wtg_h, gcn_b, gcn_b, gcn_b,
        xh, xw, NN, D, D, NN);

    // ---- GCN aggregation (needs xw + sim)
    cudaStreamWaitEvent(0, evSim, 0);
    {
        dim3 g(S, D / 128);
        k_gcn_first<<<g, 128>>>(gcn_b);
    }

    // ---- GatedGraphConv: msg chain on s2 overlaps the gh GEMM on stream 0
    cudaStreamWaitEvent(0, evW2, 0);
    for (int l = 0; l < 2; l++) {
        cudaEventRecord(evX[l], 0);
        cudaStreamWaitEvent(s2, evX[l], 0);
        k_colsum<<<3, 256, 0, s2>>>();
        k_mvec<<<3, 256, 0, s2>>>(ggc_W + (size_t)l * D * D);
        k_gi<<<H3 / 8, 256, 0, s2>>>(gru_wih, gru_bih);
        cudaEventRecord(evGi[l], s2);

        h_gemm<1, true, false><<<dim3(H3 / BN, NN / BM), 256, SMEM_BYTES>>>(
            xh, whh_h, whh_h, whh_h, gru_bhh, gru_bhh, gru_bhh,
            ghh, nullptr, NN, H3, D, NN);

        cudaStreamWaitEvent(0, evGi[l], 0);
        if (l == 0) k_gru<false><<<NN * D / 512, 256>>>(gru_bih, h_feature);
        else        k_gru<true><<<NN * D / 512, 256>>>(gru_bih, h_feature);
    }

    // ---- three residual MLPs, batched over M=12288
    h_gemm<2, true, false><<<dim3(D / BN, NN / BM), 256, SMEM_BYTES>>>(
        featsh, wt1_h, wt1_h + (size_t)D * D, wt1_h + 2 * (size_t)D * D,
        rb1[0], rb1[1], rb1[2], xh, nullptr, NN, D, D, BSN);
    h_gemm<1, false, false><<<dim3(D / BN, NN / BM), 256, SMEM_BYTES>>>(
        xh, wt2_h, wt2_h + (size_t)D * D, wt2_h + 2 * (size_t)D * D,
        rb2[0], rb2[1], rb2[2], zbuf, nullptr, NN, D, D, BSN);

    // ---- LayerNorm -> d_out
    k_ln<<<NN, 256>>>(rg[0], rbeta[0], rg[1], rbeta[1], rg[2], rbeta[2], out);
}

// round 14
// speedup vs baseline: 1.0395x; 1.0395x over previous
#include <cuda_runtime.h>
#include <cuda_fp16.h>
#include <math.h>
#include <stdint.h>

// Problem constants
constexpr int D   = 768;
constexpr int S   = 128;
constexpr int BSN = 4096;    // B*S
constexpr int NN  = 12288;   // 3*B*S
constexpr int H3  = 2304;    // 3*D

// Scratch (device globals — allocation-free rule)
__device__ float  g_xw[S * D];            // raw xw for first 128 rows only
__device__ float  g_z[NN * D];            // MLP pre-LN output
__device__ __half g_ghh[(size_t)NN * H3]; // GRU gh (fp16)
__device__ float  g_feats32[S * D];
__device__ __half g_featsh[NN * D];       // feats fp16; reused as y fp16
__device__ __half g_xh[NN * D];           // x state fp16; reused as MLP hidden
__device__ __half g_whh_h[H3 * D];
__device__ __half g_wtg_h[D * D];
__device__ __half g_wt1_h[3 * D * D];
__device__ __half g_wt2_h[3 * D * D];
__device__ float  g_sim[S * S];
__device__ float  g_nrm[S];
__device__ float  g_dinv[S];
__device__ float  g_deginv[S];
__device__ float  g_svec[D];
__device__ float  g_mvec[D];
__device__ float  g_gi[H3];

// ============================ mma.sync helpers =============================
__device__ __forceinline__ uint32_t smem_u32(const void* p) {
    uint32_t a;
    asm("{ .reg .u64 t; cvta.to.shared.u64 t, %1; cvt.u32.u64 %0, t; }"
        : "=r"(a) : "l"(p));
    return a;
}
__device__ __forceinline__ void ldm_x4(uint32_t& r0, uint32_t& r1,
                                       uint32_t& r2, uint32_t& r3, uint32_t addr) {
    asm volatile("ldmatrix.sync.aligned.m8n8.x4.shared.b16 {%0,%1,%2,%3}, [%4];"
                 : "=r"(r0), "=r"(r1), "=r"(r2), "=r"(r3) : "r"(addr));
}
__device__ __forceinline__ void mma_f16(float* c, const uint32_t* a,
                                        const uint32_t* b) {
    asm volatile(
        "mma.sync.aligned.m16n8k16.row.col.f32.f16.f16.f32 "
        "{%0,%1,%2,%3}, {%4,%5,%6,%7}, {%8,%9}, {%0,%1,%2,%3};"
        : "+f"(c[0]), "+f"(c[1]), "+f"(c[2]), "+f"(c[3])
        : "r"(a[0]), "r"(a[1]), "r"(a[2]), "r"(a[3]), "r"(b[0]), "r"(b[1]));
}
__device__ __forceinline__ float sigm(float v) { return 1.f / (1.f + expf(-v)); }
#define CP16(dst, src) \
    asm volatile("cp.async.cg.shared.global [%0], [%1], 16;" :: "r"(dst), "l"(src))
#define CP_COMMIT() asm volatile("cp.async.commit_group;" ::: "memory")
#define CP_WAIT1()  asm volatile("cp.async.wait_group 1;" ::: "memory")

// ===========================================================================
// fp16 mma.sync GEMM (R12-proven): C[m,n] = sum_k A[m,k]*B[n,k]
// Block 128x256, BK=32, 8 warps (2m x 4n), warp tile 64x64, 3-stage cp.async.
// EPI: 0 none, 1 bias, 2 bias+relu. OUTH: fp16 output.
// GCN: bm==0 tile writes raw fp32 to Caux; others bias+relu fp16 to Cv.
// ===========================================================================
constexpr int BM = 128, BN = 256, BK = 32;
constexpr int ROWB2 = 80;
constexpr uint32_t A_BYTES = BM * ROWB2;              // 10240
constexpr uint32_t STAGE_BYTES = (BM + BN) * ROWB2;   // 30720
constexpr uint32_t SMEM_BYTES = 3 * STAGE_BYTES;      // 92160

template <int EPI, bool OUTH, bool GCN>
__global__ void __launch_bounds__(256, 1) h_gemm(
    const __half* __restrict__ A,
    const __half* __restrict__ B0, const __half* __restrict__ B1,
    const __half* __restrict__ B2,
    const float* __restrict__ bias0, const float* __restrict__ bias1,
    const float* __restrict__ bias2,
    void* __restrict__ Cv, float* __restrict__ Caux,
    int M, int N, int K, int rowSeg)
{
    extern __shared__ char smem[];
    const int bn = blockIdx.x * BN;
    const int bm = blockIdx.y * BM;
    const int seg = bm / rowSeg;
    const __half* Bp  = (seg == 0) ? B0 : ((seg == 1) ? B1 : B2);
    const float* bias = (seg == 0) ? bias0 : ((seg == 1) ? bias1 : bias2);

    const int tid  = threadIdx.x;
    const int lane = tid & 31;
    const int wid  = tid >> 5;
    const int wm   = (wid >> 2) * 64;
    const int wn   = (wid & 3) * 64;

    const uint32_t sS = smem_u32(smem);

    const int lr = tid >> 1;
    const int ko = (tid & 1) * 16;
    const __half* Agl = A  + (size_t)(bm + lr) * K + ko;
    const __half* Bgl = Bp + (size_t)(bn + lr) * K + ko;
    const uint32_t aDst = (uint32_t)lr * ROWB2 + ko * 2;
    const uint32_t bDst = A_BYTES + (uint32_t)lr * ROWB2 + ko * 2;

#define LOAD_STAGE(s, kb) do { \
    const int _k0 = (kb) * BK; \
    const uint32_t _base = sS + (uint32_t)(s) * STAGE_BYTES; \
    const __half* _a = Agl + _k0; \
    CP16(_base + aDst, _a); CP16(_base + aDst + 16, _a + 8); \
    const __half* _b = Bgl + _k0; \
    CP16(_base + bDst, _b); CP16(_base + bDst + 16, _b + 8); \
    _b += (size_t)128 * K; \
    CP16(_base + bDst + 128 * ROWB2, _b); \
    CP16(_base + bDst + 128 * ROWB2 + 16, _b + 8); \
} while (0)

    float c[4][8][4];
#pragma unroll
    for (int i = 0; i < 4; i++)
#pragma unroll
        for (int j = 0; j < 8; j++)
#pragma unroll
            for (int q = 0; q < 4; q++) c[i][j][q] = 0.f;

    LOAD_STAGE(0, 0); CP_COMMIT();
    LOAD_STAGE(1, 1); CP_COMMIT();

    const uint32_t aOff = (uint32_t)(wm + (lane & 15)) * ROWB2 + (lane >> 4) * 16;
    const uint32_t bOff = (uint32_t)(wn + (lane & 7) + ((lane >> 4) << 3)) * ROWB2
                          + ((lane >> 3) & 1) * 16;

    const int NS = K / BK;
    for (int ks = 0; ks < NS; ks++) {
        CP_WAIT1();
        __syncthreads();
        if (ks + 2 < NS) {
            LOAD_STAGE((ks + 2) % 3, ks + 2);
            CP_COMMIT();
        }
        const uint32_t aB = sS + (uint32_t)(ks % 3) * STAGE_BYTES;
        const uint32_t bB = aB + A_BYTES;
#pragma unroll
        for (int kh = 0; kh < 2; kh++) {
            uint32_t af[4][4], bf[8][2];
#pragma unroll
            for (int mt = 0; mt < 4; mt++)
                ldm_x4(af[mt][0], af[mt][1], af[mt][2], af[mt][3],
                       aB + aOff + kh * 32 + (uint32_t)mt * (16 * ROWB2));
#pragma unroll
            for (int jp = 0; jp < 4; jp++) {
                uint32_t r0, r1, r2, r3;
                ldm_x4(r0, r1, r2, r3,
                       bB + bOff + kh * 32 + (uint32_t)jp * (16 * ROWB2));
                bf[2 * jp][0] = r0;     bf[2 * jp][1] = r1;
                bf[2 * jp + 1][0] = r2; bf[2 * jp + 1][1] = r3;
            }
#pragma unroll
            for (int mt = 0; mt < 4; mt++)
#pragma unroll
                for (int nt = 0; nt < 8; nt++)
                    mma_f16(c[mt][nt], af[mt], bf[nt]);
        }
    }

    const int er = lane >> 2;
    const int ec = (lane & 3) * 2;
    const bool rawTile = GCN && (bm == 0);
#pragma unroll
    for (int mt = 0; mt < 4; mt++) {
        const int m = bm + wm + mt * 16 + er;
#pragma unroll
        for (int nt = 0; nt < 8; nt++) {
            const int n = bn + wn + nt * 8 + ec;
            float2 v0 = make_float2(c[mt][nt][0], c[mt][nt][1]);
            float2 v1 = make_float2(c[mt][nt][2], c[mt][nt][3]);
            if (rawTile) {
                *(float2*)(Caux + (size_t)m * N + n)       = v0;
                *(float2*)(Caux + (size_t)(m + 8) * N + n) = v1;
                continue;
            }
            if (EPI >= 1) {
                float b0 = bias[n], b1 = bias[n + 1];
                v0.x += b0; v0.y += b1;
                v1.x += b0; v1.y += b1;
            }
            if (EPI == 2) {
                v0.x = fmaxf(v0.x, 0.f); v0.y = fmaxf(v0.y, 0.f);
                v1.x = fmaxf(v1.x, 0.f); v1.y = fmaxf(v1.y, 0.f);
            }
            if (OUTH) {
                __half* Ch = (__half*)Cv;
                *(__half2*)(Ch + (size_t)m * N + n)       = __floats2half2_rn(v0.x, v0.y);
                *(__half2*)(Ch + (size_t)(m + 8) * N + n) = __floats2half2_rn(v1.x, v1.y);
            } else {
                float* Cf = (float*)Cv;
                *(float2*)(Cf + (size_t)m * N + n)       = v0;
                *(float2*)(Cf + (size_t)(m + 8) * N + n) = v1;
            }
        }
    }
#undef LOAD_STAGE
}

// ============================ small kernels ================================
__global__ void k_transpose_h(const float* __restrict__ src, __half* __restrict__ dst)
{
    __shared__ float t[32][33];
    int bx = blockIdx.x * 32, by = blockIdx.y * 32;
    int x = bx + threadIdx.x;
#pragma unroll
    for (int j = 0; j < 32; j += 8)
        t[threadIdx.y + j][threadIdx.x] = src[(size_t)(by + threadIdx.y + j) * D + x];
    __syncthreads();
    int ox = by + threadIdx.x;
#pragma unroll
    for (int j = 0; j < 32; j += 8)
        dst[(size_t)(bx + threadIdx.y + j) * D + ox] = __float2half(t[threadIdx.x][threadIdx.y + j]);
}

__global__ void k_cvt_h(const float* __restrict__ src, __half* __restrict__ dst)
{
    int i = blockIdx.x * 256 + threadIdx.x;
    dst[i] = __float2half(src[i]);
}

__global__ void k_gather(const float* __restrict__ a, const float* __restrict__ b,
                         const float* __restrict__ c)
{
    int o = blockIdx.x * 256 + threadIdx.x;
    int n = o / D;
    int d = o - n * D;
    int t = d % 3;
    const float* s = (t == 0) ? a : ((t == 1) ? b : c);
    float v = s[n * (D / 3) + d / 3];
    g_featsh[o] = __float2half(v);
    if (o < S * D) g_feats32[o] = v;
}

__global__ void k_norm()
{
    int i = blockIdx.x;
    float s = 0.f;
    for (int k = threadIdx.x; k < D; k += 256) {
        float v = g_feats32[i * D + k];
        s = fmaf(v, v, s);
    }
    __shared__ float sh[256];
    sh[threadIdx.x] = s; __syncthreads();
    for (int t = 128; t > 0; t >>= 1) {
        if (threadIdx.x < t) sh[threadIdx.x] += sh[threadIdx.x + t];
        __syncthreads();
    }
    if (threadIdx.x == 0) g_nrm[i] = fmaxf(sqrtf(sh[0]), 1e-8f);
}

__global__ void k_sim()
{
    int i = blockIdx.x;
    __shared__ float fi[D];
    for (int k = threadIdx.x; k < D; k += 256) fi[k] = g_feats32[i * D + k];
    __syncthreads();
    int warp = threadIdx.x >> 5, lane = threadIdx.x & 31;
    float ni = g_nrm[i];
    for (int jj = 0; jj < 16; jj++) {
        int j = warp * 16 + jj;
        float s = 0.f;
        for (int k = lane; k < D; k += 32) s = fmaf(fi[k], g_feats32[j * D + k], s);
        for (int o = 16; o > 0; o >>= 1) s += __shfl_down_sync(0xffffffffu, s, o);
        if (lane == 0) g_sim[i * S + j] = s / (ni * g_nrm[j]);
    }
}

__global__ void k_simnorm()
{
    __shared__ float smn[256], smx[256];
    int tid = threadIdx.x;
    float mn = 1e30f, mx = -1e30f;
    for (int e = tid; e < S * S; e += 256) {
        float v = g_sim[e];
        mn = fminf(mn, v); mx = fmaxf(mx, v);
    }
    smn[tid] = mn; smx[tid] = mx;
    __syncthreads();
    for (int t = 128; t > 0; t >>= 1) {
        if (tid < t) {
            smn[tid] = fminf(smn[tid], smn[tid + t]);
            smx[tid] = fmaxf(smx[tid], smx[tid + t]);
        }
        __syncthreads();
    }
    float lo = smn[0];
    float inv = 1.f / (smx[0] - smn[0]);
    __syncthreads();
    for (int e = tid; e < S * S; e += 256) g_sim[e] = (g_sim[e] - lo) * inv;
    __syncthreads();
    if (tid < S) {
        float dg = 1.f;
        for (int i = 0; i < S; i++) dg += g_sim[i * S + tid];
        g_dinv[tid]   = rsqrtf(dg);
        g_deginv[tid] = 1.f / dg;
    }
}

__global__ void k_gcn_first(const float* __restrict__ gcn_b)
{
    int c = blockIdx.x;
    int d = blockIdx.y * 128 + threadIdx.x;
    __shared__ float col[S];
    col[threadIdx.x] = g_dinv[threadIdx.x] * g_sim[threadIdx.x * S + c];
    __syncthreads();
    float acc = 0.f;
#pragma unroll 8
    for (int i = 0; i < S; i++) acc = fmaf(col[i], g_xw[i * D + d], acc);
    float v = g_dinv[c] * acc + g_xw[c * D + d] * g_deginv[c] + gcn_b[d];
    g_xh[c * D + d] = __float2half(fmaxf(v, 0.f));
}

__global__ void k_colsum()
{
    int d = blockIdx.x * 256 + threadIdx.x;
    float s = 0.f;
    for (int r = 0; r < S; r++) s += __half2float(g_xh[r * D + d]);
    g_svec[d] = s;
}

__global__ void k_mvec(const float* __restrict__ W)
{
    int d = blockIdx.x * 256 + threadIdx.x;
    float acc = 0.f;
    for (int k = 0; k < D; k++) acc = fmaf(g_svec[k], W[k * D + d], acc);
    g_mvec[d] = acc;
}

__global__ void k_gi(const float* __restrict__ wih, const float* __restrict__ bih)
{
    int warp = threadIdx.x >> 5, lane = threadIdx.x & 31;
    int o = blockIdx.x * 8 + warp;
    float s = 0.f;
    for (int k = lane; k < D; k += 32) s = fmaf(g_mvec[k], wih[o * D + k], s);
    for (int off = 16; off > 0; off >>= 1) s += __shfl_down_sync(0xffffffffu, s, off);
    if (lane == 0) g_gi[o] = s + bih[o];
}

template <bool LAST>
__global__ void k_gru(const float* __restrict__ bih, const float* __restrict__ hfeat)
{
    int p = blockIdx.x * 256 + threadIdx.x;   // pair index
    int o = p * 2;
    int n = o / D;
    int d = o - n * D;
    float gir0, gir1, giz0, giz1, gin0, gin1;
    if (n < S) {
        gir0 = g_gi[d];        gir1 = g_gi[d + 1];
        giz0 = g_gi[D + d];    giz1 = g_gi[D + d + 1];
        gin0 = g_gi[2*D + d];  gin1 = g_gi[2*D + d + 1];
    } else {
        gir0 = bih[d];         gir1 = bih[d + 1];
        giz0 = bih[D + d];     giz1 = bih[D + d + 1];
        gin0 = bih[2*D + d];   gin1 = bih[2*D + d + 1];
    }
    const size_t gb = (size_t)n * H3;
    float2 hr = __half22float2(*(const __half2*)(g_ghh + gb + d));
    float2 hz = __half22float2(*(const __half2*)(g_ghh + gb + D + d));
    float2 hn = __half22float2(*(const __half2*)(g_ghh + gb + 2*D + d));
    float2 h  = __half22float2(*(const __half2*)(g_xh + o));
    float r0 = sigm(gir0 + hr.x), r1 = sigm(gir1 + hr.y);
    float z0 = sigm(giz0 + hz.x), z1 = sigm(giz1 + hz.y);
    float n0 = tanhf(gin0 + r0 * hn.x), n1 = tanhf(gin1 + r1 * hn.y);
    float o0 = (1.f - z0) * n0 + z0 * h.x;
    float o1 = (1.f - z1) * n1 + z1 * h.y;
    if (LAST) {
        int hb = o % (BSN * D);
        float2 hf = *(const float2*)(hfeat + hb);
        *(__half2*)(g_featsh + o) =
            __floats2half2_rn(hf.x + fmaxf(o0, 0.f), hf.y + fmaxf(o1, 0.f));
    } else {
        *(__half2*)(g_xh + o) = __floats2half2_rn(o0, o1);
    }
}

__global__ void k_ln(const float* __restrict__ g1, const float* __restrict__ be1,
                     const float* __restrict__ g2, const float* __restrict__ be2,
                     const float* __restrict__ g3, const float* __restrict__ be3,
                     float* __restrict__ out)
{
    int r = blockIdx.x;
    int t = r / BSN;
    const float* gg = (t == 0) ? g1 : ((t == 1) ? g2 : g3);
    const float* bb = (t == 0) ? be1 : ((t == 1) ? be2 : be3);
    const float* z = g_z + (size_t)r * D;
    int tid = threadIdx.x;
    float v0 = z[tid], v1 = z[tid + 256], v2 = z[tid + 512];
    __shared__ float sh[256];
    sh[tid] = v0 + v1 + v2; __syncthreads();
    for (int s = 128; s > 0; s >>= 1) {
        if (tid < s) sh[tid] += sh[tid + s];
        __syncthreads();
    }
    float mu = sh[0] * (1.f / 768.f);
    __syncthreads();
    float d0 = v0 - mu, d1 = v1 - mu, d2 = v2 - mu;
    sh[tid] = d0 * d0 + d1 * d1 + d2 * d2; __syncthreads();
    for (int s = 128; s > 0; s >>= 1) {
        if (tid < s) sh[tid] += sh[tid + s];
        __syncthreads();
    }
    float rstd = rsqrtf(sh[0] * (1.f / 768.f) + 1e-5f);
    float* o = out + (size_t)r * D;
    o[tid]       = d0 * rstd * gg[tid]       + bb[tid];
    o[tid + 256] = d1 * rstd * gg[tid + 256] + bb[tid + 256];
    o[tid + 512] = d2 * rstd * gg[tid + 512] + bb[tid + 512];
}

// ---------------------------------------------------------------------------
extern "C" void kernel_launch(void* const* d_in, const int* in_sizes, int n_in,
                              void* d_out, int out_size)
{
    const float* h_feature = (const float*)d_in[0];
    const float* h_con     = (const float*)d_in[1];
    const float* h_dep     = (const float*)d_in[2];
    const float* h_sem     = (const float*)d_in[3];
    const float* gcn_W     = (const float*)d_in[4];
    const float* gcn_b     = (const float*)d_in[5];
    const float* ggc_W     = (const float*)d_in[6];
    const float* gru_wih   = (const float*)d_in[7];
    const float* gru_whh   = (const float*)d_in[8];
    const float* gru_bih   = (const float*)d_in[9];
    const float* gru_bhh   = (const float*)d_in[10];
    const float* rW1[3]   = {(const float*)d_in[11], (const float*)d_in[17], (const float*)d_in[23]};
    const float* rb1[3]   = {(const float*)d_in[12], (const float*)d_in[18], (const float*)d_in[24]};
    const float* rW2[3]   = {(const float*)d_in[13], (const float*)d_in[19], (const float*)d_in[25]};
    const float* rb2[3]   = {(const float*)d_in[14], (const float*)d_in[20], (const float*)d_in[26]};
    const float* rg[3]    = {(const float*)d_in[15], (const float*)d_in[21], (const float*)d_in[27]};
    const float* rbeta[3] = {(const float*)d_in[16], (const float*)d_in[22], (const float*)d_in[28]};
    float* out = (float*)d_out;

    float *xw, *zbuf;
    __half *ghh, *featsh, *xh, *whh_h, *wtg_h, *wt1_h, *wt2_h;
    cudaGetSymbolAddress((void**)&xw,     g_xw);
    cudaGetSymbolAddress((void**)&zbuf,   g_z);
    cudaGetSymbolAddress((void**)&ghh,    g_ghh);
    cudaGetSymbolAddress((void**)&featsh, g_featsh);
    cudaGetSymbolAddress((void**)&xh,     g_xh);
    cudaGetSymbolAddress((void**)&whh_h,  g_whh_h);
    cudaGetSymbolAddress((void**)&wtg_h,  g_wtg_h);
    cudaGetSymbolAddress((void**)&wt1_h,  g_wt1_h);
    cudaGetSymbolAddress((void**)&wt2_h,  g_wt2_h);

    // One-time stream/event setup (runs during the un-captured correctness call)
    static cudaStream_t s1 = nullptr, s2 = nullptr;
    static cudaEvent_t evRoot, evW1, evW2, evG, evSim, evX[2], evGi[2];
    static cudaEvent_t evM1[3], evM2;
    if (!s1) {
        cudaStreamCreateWithFlags(&s1, cudaStreamNonBlocking);
        cudaStreamCreateWithFlags(&s2, cudaStreamNonBlocking);
        cudaEventCreateWithFlags(&evRoot, cudaEventDisableTiming);
        cudaEventCreateWithFlags(&evW1,   cudaEventDisableTiming);
        cudaEventCreateWithFlags(&evW2,   cudaEventDisableTiming);
        cudaEventCreateWithFlags(&evG,    cudaEventDisableTiming);
        cudaEventCreateWithFlags(&evSim,  cudaEventDisableTiming);
        cudaEventCreateWithFlags(&evM2,   cudaEventDisableTiming);
        for (int i = 0; i < 2; i++) {
            cudaEventCreateWithFlags(&evX[i],  cudaEventDisableTiming);
            cudaEventCreateWithFlags(&evGi[i], cudaEventDisableTiming);
        }
        for (int i = 0; i < 3; i++)
            cudaEventCreateWithFlags(&evM1[i], cudaEventDisableTiming);
        cudaFuncSetAttribute((const void*)h_gemm<2, true, true>,
                             cudaFuncAttributeMaxDynamicSharedMemorySize, SMEM_BYTES);
        cudaFuncSetAttribute((const void*)h_gemm<1, true, false>,
                             cudaFuncAttributeMaxDynamicSharedMemorySize, SMEM_BYTES);
        cudaFuncSetAttribute((const void*)h_gemm<2, true, false>,
                             cudaFuncAttributeMaxDynamicSharedMemorySize, SMEM_BYTES);
        cudaFuncSetAttribute((const void*)h_gemm<1, false, false>,
                             cudaFuncAttributeMaxDynamicSharedMemorySize, SMEM_BYTES);
    }

    dim3 tb(32, 8);
    dim3 tg(D / 32, D / 32);

    // ---- fork weight prep onto s1 (no data deps)
    cudaEventRecord(evRoot, 0);
    cudaStreamWaitEvent(s1, evRoot, 0);
    k_transpose_h<<<tg, tb, 0, s1>>>(gcn_W, wtg_h);
    cudaEventRecord(evW1, s1);   // wtg ready (needed by GEMM1)
    for (int t = 0; t < 3; t++) {
        k_transpose_h<<<tg, tb, 0, s1>>>(rW1[t], wt1_h + (size_t)t * D * D);
        k_transpose_h<<<tg, tb, 0, s1>>>(rW2[t], wt2_h + (size_t)t * D * D);
    }
    k_cvt_h<<<H3 * D / 256, 256, 0, s1>>>(gru_whh, whh_h);
    cudaEventRecord(evW2, s1);   // all other weights ready

    // ---- main stream: gather, then fork the sim chain onto s2
    k_gather<<<NN * D / 256, 256>>>(h_con, h_dep, h_sem);
    cudaEventRecord(evG, 0);
    cudaStreamWaitEvent(s2, evG, 0);
    k_norm<<<S, 256, 0, s2>>>();
    k_sim<<<S, 256, 0, s2>>>();
    k_simnorm<<<1, 256, 0, s2>>>();
    cudaEventRecord(evSim, s2);

    // ---- GEMM1 (xw) overlaps with the sim chain
    cudaStreamWaitEvent(0, evW1, 0);
    h_gemm<2, true, true><<<dim3(D / BN, NN / BM), 256, SMEM_BYTES>>>(
        featsh, wtg_h, wtg_h, wtg_h, gcn_b, gcn_b, gcn_b,
        xh, xw, NN, D, D, NN);

    // ---- GCN aggregation (needs xw + sim)
    cudaStreamWaitEvent(0, evSim, 0);
    {
        dim3 g(S, D / 128);
        k_gcn_first<<<g, 128>>>(gcn_b);
    }

    // ---- GatedGraphConv: msg chain on s2 overlaps the gh GEMM on stream 0
    cudaStreamWaitEvent(0, evW2, 0);
    for (int l = 0; l < 2; l++) {
        cudaEventRecord(evX[l], 0);
        cudaStreamWaitEvent(s2, evX[l], 0);
        k_colsum<<<3, 256, 0, s2>>>();
        k_mvec<<<3, 256, 0, s2>>>(ggc_W + (size_t)l * D * D);
        k_gi<<<H3 / 8, 256, 0, s2>>>(gru_wih, gru_bih);
        cudaEventRecord(evGi[l], s2);

        h_gemm<1, true, false><<<dim3(H3 / BN, NN / BM), 256, SMEM_BYTES>>>(
            xh, whh_h, whh_h, whh_h, gru_bhh, gru_bhh, gru_bhh,
            ghh, nullptr, NN, H3, D, NN);

        cudaStreamWaitEvent(0, evGi[l], 0);
        if (l == 0) k_gru<false><<<NN * D / 512, 256>>>(gru_bih, h_feature);
        else        k_gru<true><<<NN * D / 512, 256>>>(gru_bih, h_feature);
    }

    // ---- three residual MLPs, segment-pipelined across streams:
    //      GEMM1(seg t) on stream 0; GEMM2(seg t) on s1 as soon as seg t done.
    //      Fills GEMM1 wave-tail bubbles with GEMM2 work.
    for (int t = 0; t < 3; t++) {
        const size_t off = (size_t)t * BSN * D;
        h_gemm<2, true, false><<<dim3(D / BN, BSN / BM), 256, SMEM_BYTES>>>(
            featsh + off, wt1_h + (size_t)t * D * D, wt1_h, wt1_h,
            rb1[t], rb1[t], rb1[t], xh + off, nullptr, BSN, D, D, BSN);
        cudaEventRecord(evM1[t], 0);
        cudaStreamWaitEvent(s1, evM1[t], 0);
        h_gemm<1, false, false><<<dim3(D / BN, BSN / BM), 256, SMEM_BYTES, s1>>>(
            xh + off, wt2_h + (size_t)t * D * D, wt2_h, wt2_h,
            rb2[t], rb2[t], rb2[t], zbuf + off, nullptr, BSN, D, D, BSN);
    }
    cudaEventRecord(evM2, s1);
    cudaStreamWaitEvent(0, evM2, 0);

    // ---- LayerNorm -> d_out
    k_ln<<<NN, 256>>>(rg[0], rbeta[0], rg[1], rbeta[1], rg[2], rbeta[2], out);
}

// round 15
// speedup vs baseline: 1.0844x; 1.0431x over previous
#include <cuda_runtime.h>
#include <cuda_fp16.h>
#include <math.h>
#include <stdint.h>

// Problem constants
constexpr int D   = 768;
constexpr int S   = 128;
constexpr int BSN = 4096;    // B*S
constexpr int NN  = 12288;   // 3*B*S
constexpr int H3  = 2304;    // 3*D

// Scratch (device globals — allocation-free rule)
__device__ float  g_xw[S * D];            // raw xw for first 128 rows only
__device__ __half g_ghh[(size_t)NN * H3]; // GRU gh (fp16); reused as z fp16
__device__ float  g_feats32[S * D];
__device__ __half g_featsh[NN * D];       // feats fp16; reused as y fp16
__device__ __half g_xh[NN * D];           // x state fp16; reused as MLP hidden
__device__ __half g_whh_h[H3 * D];
__device__ __half g_wtg_h[D * D];
__device__ __half g_wt1_h[3 * D * D];
__device__ __half g_wt2_h[3 * D * D];
__device__ float  g_sim[S * S];
__device__ float  g_nrm[S];
__device__ float  g_dinv[S];
__device__ float  g_deginv[S];
__device__ float  g_svec[D];
__device__ float  g_mvec[D];
__device__ float  g_gi[H3];

// ============================ mma.sync helpers =============================
__device__ __forceinline__ uint32_t smem_u32(const void* p) {
    uint32_t a;
    asm("{ .reg .u64 t; cvta.to.shared.u64 t, %1; cvt.u32.u64 %0, t; }"
        : "=r"(a) : "l"(p));
    return a;
}
__device__ __forceinline__ void ldm_x4(uint32_t& r0, uint32_t& r1,
                                       uint32_t& r2, uint32_t& r3, uint32_t addr) {
    asm volatile("ldmatrix.sync.aligned.m8n8.x4.shared.b16 {%0,%1,%2,%3}, [%4];"
                 : "=r"(r0), "=r"(r1), "=r"(r2), "=r"(r3) : "r"(addr));
}
__device__ __forceinline__ void mma_f16(float* c, const uint32_t* a,
                                        const uint32_t* b) {
    asm volatile(
        "mma.sync.aligned.m16n8k16.row.col.f32.f16.f16.f32 "
        "{%0,%1,%2,%3}, {%4,%5,%6,%7}, {%8,%9}, {%0,%1,%2,%3};"
        : "+f"(c[0]), "+f"(c[1]), "+f"(c[2]), "+f"(c[3])
        : "r"(a[0]), "r"(a[1]), "r"(a[2]), "r"(a[3]), "r"(b[0]), "r"(b[1]));
}
__device__ __forceinline__ float sigm(float v) { return 1.f / (1.f + expf(-v)); }
#define CP16(dst, src) \
    asm volatile("cp.async.cg.shared.global [%0], [%1], 16;" :: "r"(dst), "l"(src))
#define CP_COMMIT() asm volatile("cp.async.commit_group;" ::: "memory")
#define CP_WAIT1()  asm volatile("cp.async.wait_group 1;" ::: "memory")

// ===========================================================================
// fp16 mma.sync GEMM (R12-proven): C[m,n] = sum_k A[m,k]*B[n,k]
// Block 128x256, BK=32, 8 warps (2m x 4n), warp tile 64x64, 3-stage cp.async.
// EPI: 0 none, 1 bias, 2 bias+relu. OUTH: fp16 output.
// GCN: bm==0 tile writes raw fp32 to Caux; others bias+relu fp16 to Cv.
// ===========================================================================
constexpr int BM = 128, BN = 256, BK = 32;
constexpr int ROWB2 = 80;
constexpr uint32_t A_BYTES = BM * ROWB2;              // 10240
constexpr uint32_t STAGE_BYTES = (BM + BN) * ROWB2;   // 30720
constexpr uint32_t SMEM_BYTES = 3 * STAGE_BYTES;      // 92160

template <int EPI, bool OUTH, bool GCN>
__global__ void __launch_bounds__(256, 1) h_gemm(
    const __half* __restrict__ A,
    const __half* __restrict__ B0, const __half* __restrict__ B1,
    const __half* __restrict__ B2,
    const float* __restrict__ bias0, const float* __restrict__ bias1,
    const float* __restrict__ bias2,
    void* __restrict__ Cv, float* __restrict__ Caux,
    int M, int N, int K, int rowSeg)
{
    extern __shared__ char smem[];
    const int bn = blockIdx.x * BN;
    const int bm = blockIdx.y * BM;
    const int seg = bm / rowSeg;
    const __half* Bp  = (seg == 0) ? B0 : ((seg == 1) ? B1 : B2);
    const float* bias = (seg == 0) ? bias0 : ((seg == 1) ? bias1 : bias2);

    const int tid  = threadIdx.x;
    const int lane = tid & 31;
    const int wid  = tid >> 5;
    const int wm   = (wid >> 2) * 64;
    const int wn   = (wid & 3) * 64;

    const uint32_t sS = smem_u32(smem);

    const int lr = tid >> 1;
    const int ko = (tid & 1) * 16;
    const __half* Agl = A  + (size_t)(bm + lr) * K + ko;
    const __half* Bgl = Bp + (size_t)(bn + lr) * K + ko;
    const uint32_t aDst = (uint32_t)lr * ROWB2 + ko * 2;
    const uint32_t bDst = A_BYTES + (uint32_t)lr * ROWB2 + ko * 2;

#define LOAD_STAGE(s, kb) do { \
    const int _k0 = (kb) * BK; \
    const uint32_t _base = sS + (uint32_t)(s) * STAGE_BYTES; \
    const __half* _a = Agl + _k0; \
    CP16(_base + aDst, _a); CP16(_base + aDst + 16, _a + 8); \
    const __half* _b = Bgl + _k0; \
    CP16(_base + bDst, _b); CP16(_base + bDst + 16, _b + 8); \
    _b += (size_t)128 * K; \
    CP16(_base + bDst + 128 * ROWB2, _b); \
    CP16(_base + bDst + 128 * ROWB2 + 16, _b + 8); \
} while (0)

    float c[4][8][4];
#pragma unroll
    for (int i = 0; i < 4; i++)
#pragma unroll
        for (int j = 0; j < 8; j++)
#pragma unroll
            for (int q = 0; q < 4; q++) c[i][j][q] = 0.f;

    LOAD_STAGE(0, 0); CP_COMMIT();
    LOAD_STAGE(1, 1); CP_COMMIT();

    const uint32_t aOff = (uint32_t)(wm + (lane & 15)) * ROWB2 + (lane >> 4) * 16;
    const uint32_t bOff = (uint32_t)(wn + (lane & 7) + ((lane >> 4) << 3)) * ROWB2
                          + ((lane >> 3) & 1) * 16;

    const int NS = K / BK;
    for (int ks = 0; ks < NS; ks++) {
        CP_WAIT1();
        __syncthreads();
        if (ks + 2 < NS) {
            LOAD_STAGE((ks + 2) % 3, ks + 2);
            CP_COMMIT();
        }
        const uint32_t aB = sS + (uint32_t)(ks % 3) * STAGE_BYTES;
        const uint32_t bB = aB + A_BYTES;
#pragma unroll
        for (int kh = 0; kh < 2; kh++) {
            uint32_t af[4][4], bf[8][2];
#pragma unroll
            for (int mt = 0; mt < 4; mt++)
                ldm_x4(af[mt][0], af[mt][1], af[mt][2], af[mt][3],
                       aB + aOff + kh * 32 + (uint32_t)mt * (16 * ROWB2));
#pragma unroll
            for (int jp = 0; jp < 4; jp++) {
                uint32_t r0, r1, r2, r3;
                ldm_x4(r0, r1, r2, r3,
                       bB + bOff + kh * 32 + (uint32_t)jp * (16 * ROWB2));
                bf[2 * jp][0] = r0;     bf[2 * jp][1] = r1;
                bf[2 * jp + 1][0] = r2; bf[2 * jp + 1][1] = r3;
            }
#pragma unroll
            for (int mt = 0; mt < 4; mt++)
#pragma unroll
                for (int nt = 0; nt < 8; nt++)
                    mma_f16(c[mt][nt], af[mt], bf[nt]);
        }
    }

    const int er = lane >> 2;
    const int ec = (lane & 3) * 2;
    const bool rawTile = GCN && (bm == 0);
#pragma unroll
    for (int mt = 0; mt < 4; mt++) {
        const int m = bm + wm + mt * 16 + er;
#pragma unroll
        for (int nt = 0; nt < 8; nt++) {
            const int n = bn + wn + nt * 8 + ec;
            float2 v0 = make_float2(c[mt][nt][0], c[mt][nt][1]);
            float2 v1 = make_float2(c[mt][nt][2], c[mt][nt][3]);
            if (rawTile) {
                *(float2*)(Caux + (size_t)m * N + n)       = v0;
                *(float2*)(Caux + (size_t)(m + 8) * N + n) = v1;
                continue;
            }
            if (EPI >= 1) {
                float b0 = bias[n], b1 = bias[n + 1];
                v0.x += b0; v0.y += b1;
                v1.x += b0; v1.y += b1;
            }
            if (EPI == 2) {
                v0.x = fmaxf(v0.x, 0.f); v0.y = fmaxf(v0.y, 0.f);
                v1.x = fmaxf(v1.x, 0.f); v1.y = fmaxf(v1.y, 0.f);
            }
            if (OUTH) {
                __half* Ch = (__half*)Cv;
                *(__half2*)(Ch + (size_t)m * N + n)       = __floats2half2_rn(v0.x, v0.y);
                *(__half2*)(Ch + (size_t)(m + 8) * N + n) = __floats2half2_rn(v1.x, v1.y);
            } else {
                float* Cf = (float*)Cv;
                *(float2*)(Cf + (size_t)m * N + n)       = v0;
                *(float2*)(Cf + (size_t)(m + 8) * N + n) = v1;
            }
        }
    }
#undef LOAD_STAGE
}

// ============================ small kernels ================================
__global__ void k_transpose_h(const float* __restrict__ src, __half* __restrict__ dst)
{
    __shared__ float t[32][33];
    int bx = blockIdx.x * 32, by = blockIdx.y * 32;
    int x = bx + threadIdx.x;
#pragma unroll
    for (int j = 0; j < 32; j += 8)
        t[threadIdx.y + j][threadIdx.x] = src[(size_t)(by + threadIdx.y + j) * D + x];
    __syncthreads();
    int ox = by + threadIdx.x;
#pragma unroll
    for (int j = 0; j < 32; j += 8)
        dst[(size_t)(bx + threadIdx.y + j) * D + ox] = __float2half(t[threadIdx.x][threadIdx.y + j]);
}

__global__ void k_cvt_h(const float* __restrict__ src, __half* __restrict__ dst)
{
    int i = blockIdx.x * 256 + threadIdx.x;
    dst[i] = __float2half(src[i]);
}

__global__ void k_gather(const float* __restrict__ a, const float* __restrict__ b,
                         const float* __restrict__ c)
{
    int o = blockIdx.x * 256 + threadIdx.x;
    int n = o / D;
    int d = o - n * D;
    int t = d % 3;
    const float* s = (t == 0) ? a : ((t == 1) ? b : c);
    float v = s[n * (D / 3) + d / 3];
    g_featsh[o] = __float2half(v);
    if (o < S * D) g_feats32[o] = v;
}

__global__ void k_norm()
{
    int i = blockIdx.x;
    float s = 0.f;
    for (int k = threadIdx.x; k < D; k += 256) {
        float v = g_feats32[i * D + k];
        s = fmaf(v, v, s);
    }
    __shared__ float sh[256];
    sh[threadIdx.x] = s; __syncthreads();
    for (int t = 128; t > 0; t >>= 1) {
        if (threadIdx.x < t) sh[threadIdx.x] += sh[threadIdx.x + t];
        __syncthreads();
    }
    if (threadIdx.x == 0) g_nrm[i] = fmaxf(sqrtf(sh[0]), 1e-8f);
}

__global__ void k_sim()
{
    int i = blockIdx.x;
    __shared__ float fi[D];
    for (int k = threadIdx.x; k < D; k += 256) fi[k] = g_feats32[i * D + k];
    __syncthreads();
    int warp = threadIdx.x >> 5, lane = threadIdx.x & 31;
    float ni = g_nrm[i];
    for (int jj = 0; jj < 16; jj++) {
        int j = warp * 16 + jj;
        float s = 0.f;
        for (int k = lane; k < D; k += 32) s = fmaf(fi[k], g_feats32[j * D + k], s);
        for (int o = 16; o > 0; o >>= 1) s += __shfl_down_sync(0xffffffffu, s, o);
        if (lane == 0) g_sim[i * S + j] = s / (ni * g_nrm[j]);
    }
}

__global__ void k_simnorm()
{
    __shared__ float smn[256], smx[256];
    int tid = threadIdx.x;
    float mn = 1e30f, mx = -1e30f;
    for (int e = tid; e < S * S; e += 256) {
        float v = g_sim[e];
        mn = fminf(mn, v); mx = fmaxf(mx, v);
    }
    smn[tid] = mn; smx[tid] = mx;
    __syncthreads();
    for (int t = 128; t > 0; t >>= 1) {
        if (tid < t) {
            smn[tid] = fminf(smn[tid], smn[tid + t]);
            smx[tid] = fmaxf(smx[tid], smx[tid + t]);
        }
        __syncthreads();
    }
    float lo = smn[0];
    float inv = 1.f / (smx[0] - smn[0]);
    __syncthreads();
    for (int e = tid; e < S * S; e += 256) g_sim[e] = (g_sim[e] - lo) * inv;
    __syncthreads();
    if (tid < S) {
        float dg = 1.f;
        for (int i = 0; i < S; i++) dg += g_sim[i * S + tid];
        g_dinv[tid]   = rsqrtf(dg);
        g_deginv[tid] = 1.f / dg;
    }
}

__global__ void k_gcn_first(const float* __restrict__ gcn_b)
{
    int c = blockIdx.x;
    int d = blockIdx.y * 128 + threadIdx.x;
    __shared__ float col[S];
    col[threadIdx.x] = g_dinv[threadIdx.x] * g_sim[threadIdx.x * S + c];
    __syncthreads();
    float acc = 0.f;
#pragma unroll 8
    for (int i = 0; i < S; i++) acc = fmaf(col[i], g_xw[i * D + d], acc);
    float v = g_dinv[c] * acc + g_xw[c * D + d] * g_deginv[c] + gcn_b[d];
    g_xh[c * D + d] = __float2half(fmaxf(v, 0.f));
}

__global__ void k_colsum()
{
    int d = blockIdx.x * 256 + threadIdx.x;
    float s = 0.f;
    for (int r = 0; r < S; r++) s += __half2float(g_xh[r * D + d]);
    g_svec[d] = s;
}

__global__ void k_mvec(const float* __restrict__ W)
{
    int d = blockIdx.x * 256 + threadIdx.x;
    float acc = 0.f;
    for (int k = 0; k < D; k++) acc = fmaf(g_svec[k], W[k * D + d], acc);
    g_mvec[d] = acc;
}

__global__ void k_gi(const float* __restrict__ wih, const float* __restrict__ bih)
{
    int warp = threadIdx.x >> 5, lane = threadIdx.x & 31;
    int o = blockIdx.x * 8 + warp;
    float s = 0.f;
    for (int k = lane; k < D; k += 32) s = fmaf(g_mvec[k], wih[o * D + k], s);
    for (int off = 16; off > 0; off >>= 1) s += __shfl_down_sync(0xffffffffu, s, off);
    if (lane == 0) g_gi[o] = s + bih[o];
}

template <bool LAST>
__global__ void k_gru(const float* __restrict__ bih, const float* __restrict__ hfeat)
{
    int p = blockIdx.x * 256 + threadIdx.x;   // pair index
    int o = p * 2;
    int n = o / D;
    int d = o - n * D;
    float gir0, gir1, giz0, giz1, gin0, gin1;
    if (n < S) {
        gir0 = g_gi[d];        gir1 = g_gi[d + 1];
        giz0 = g_gi[D + d];    giz1 = g_gi[D + d + 1];
        gin0 = g_gi[2*D + d];  gin1 = g_gi[2*D + d + 1];
    } else {
        gir0 = bih[d];         gir1 = bih[d + 1];
        giz0 = bih[D + d];     giz1 = bih[D + d + 1];
        gin0 = bih[2*D + d];   gin1 = bih[2*D + d + 1];
    }
    const size_t gb = (size_t)n * H3;
    float2 hr = __half22float2(*(const __half2*)(g_ghh + gb + d));
    float2 hz = __half22float2(*(const __half2*)(g_ghh + gb + D + d));
    float2 hn = __half22float2(*(const __half2*)(g_ghh + gb + 2*D + d));
    float2 h  = __half22float2(*(const __half2*)(g_xh + o));
    float r0 = sigm(gir0 + hr.x), r1 = sigm(gir1 + hr.y);
    float z0 = sigm(giz0 + hz.x), z1 = sigm(giz1 + hz.y);
    float n0 = tanhf(gin0 + r0 * hn.x), n1 = tanhf(gin1 + r1 * hn.y);
    float o0 = (1.f - z0) * n0 + z0 * h.x;
    float o1 = (1.f - z1) * n1 + z1 * h.y;
    if (LAST) {
        int hb = o % (BSN * D);
        float2 hf = *(const float2*)(hfeat + hb);
        *(__half2*)(g_featsh + o) =
            __floats2half2_rn(hf.x + fmaxf(o0, 0.f), hf.y + fmaxf(o1, 0.f));
    } else {
        *(__half2*)(g_xh + o) = __floats2half2_rn(o0, o1);
    }
}

// LayerNorm reading fp16 z (stored in g_ghh's first NN*D halves)
__global__ void k_ln(const float* __restrict__ g1, const float* __restrict__ be1,
                     const float* __restrict__ g2, const float* __restrict__ be2,
                     const float* __restrict__ g3, const float* __restrict__ be3,
                     float* __restrict__ out)
{
    int r = blockIdx.x;
    int t = r / BSN;
    const float* gg = (t == 0) ? g1 : ((t == 1) ? g2 : g3);
    const float* bb = (t == 0) ? be1 : ((t == 1) ? be2 : be3);
    const __half* z = g_ghh + (size_t)r * D;
    int tid = threadIdx.x;
    float v0 = __half2float(z[tid]);
    float v1 = __half2float(z[tid + 256]);
    float v2 = __half2float(z[tid + 512]);
    __shared__ float sh[256];
    sh[tid] = v0 + v1 + v2; __syncthreads();
    for (int s = 128; s > 0; s >>= 1) {
        if (tid < s) sh[tid] += sh[tid + s];
        __syncthreads();
    }
    float mu = sh[0] * (1.f / 768.f);
    __syncthreads();
    float d0 = v0 - mu, d1 = v1 - mu, d2 = v2 - mu;
    sh[tid] = d0 * d0 + d1 * d1 + d2 * d2; __syncthreads();
    for (int s = 128; s > 0; s >>= 1) {
        if (tid < s) sh[tid] += sh[tid + s];
        __syncthreads();
    }
    float rstd = rsqrtf(sh[0] * (1.f / 768.f) + 1e-5f);
    float* o = out + (size_t)r * D;
    o[tid]       = d0 * rstd * gg[tid]       + bb[tid];
    o[tid + 256] = d1 * rstd * gg[tid + 256] + bb[tid + 256];
    o[tid + 512] = d2 * rstd * gg[tid + 512] + bb[tid + 512];
}

// ---------------------------------------------------------------------------
extern "C" void kernel_launch(void* const* d_in, const int* in_sizes, int n_in,
                              void* d_out, int out_size)
{
    const float* h_feature = (const float*)d_in[0];
    const float* h_con     = (const float*)d_in[1];
    const float* h_dep     = (const float*)d_in[2];
    const float* h_sem     = (const float*)d_in[3];
    const float* gcn_W     = (const float*)d_in[4];
    const float* gcn_b     = (const float*)d_in[5];
    const float* ggc_W     = (const float*)d_in[6];
    const float* gru_wih   = (const float*)d_in[7];
    const float* gru_whh   = (const float*)d_in[8];
    const float* gru_bih   = (const float*)d_in[9];
    const float* gru_bhh   = (const float*)d_in[10];
    const float* rW1[3]   = {(const float*)d_in[11], (const float*)d_in[17], (const float*)d_in[23]};
    const float* rb1[3]   = {(const float*)d_in[12], (const float*)d_in[18], (const float*)d_in[24]};
    const float* rW2[3]   = {(const float*)d_in[13], (const float*)d_in[19], (const float*)d_in[25]};
    const float* rb2[3]   = {(const float*)d_in[14], (const float*)d_in[20], (const float*)d_in[26]};
    const float* rg[3]    = {(const float*)d_in[15], (const float*)d_in[21], (const float*)d_in[27]};
    const float* rbeta[3] = {(const float*)d_in[16], (const float*)d_in[22], (const float*)d_in[28]};
    float* out = (float*)d_out;

    float *xw;
    __half *ghh, *featsh, *xh, *whh_h, *wtg_h, *wt1_h, *wt2_h;
    cudaGetSymbolAddress((void**)&xw,     g_xw);
    cudaGetSymbolAddress((void**)&ghh,    g_ghh);
    cudaGetSymbolAddress((void**)&featsh, g_featsh);
    cudaGetSymbolAddress((void**)&xh,     g_xh);
    cudaGetSymbolAddress((void**)&whh_h,  g_whh_h);
    cudaGetSymbolAddress((void**)&wtg_h,  g_wtg_h);
    cudaGetSymbolAddress((void**)&wt1_h,  g_wt1_h);
    cudaGetSymbolAddress((void**)&wt2_h,  g_wt2_h);

    // One-time stream/event setup (runs during the un-captured correctness call)
    static cudaStream_t s1 = nullptr, s2 = nullptr;
    static cudaEvent_t evRoot, evW1, evW2, evG, evSim, evX[2], evGi[2];
    if (!s1) {
        cudaStreamCreateWithFlags(&s1, cudaStreamNonBlocking);
        cudaStreamCreateWithFlags(&s2, cudaStreamNonBlocking);
        cudaEventCreateWithFlags(&evRoot, cudaEventDisableTiming);
        cudaEventCreateWithFlags(&evW1,   cudaEventDisableTiming);
        cudaEventCreateWithFlags(&evW2,   cudaEventDisableTiming);
        cudaEventCreateWithFlags(&evG,    cudaEventDisableTiming);
        cudaEventCreateWithFlags(&evSim,  cudaEventDisableTiming);
        for (int i = 0; i < 2; i++) {
            cudaEventCreateWithFlags(&evX[i],  cudaEventDisableTiming);
            cudaEventCreateWithFlags(&evGi[i], cudaEventDisableTiming);
        }
        cudaFuncSetAttribute((const void*)h_gemm<2, true, true>,
                             cudaFuncAttributeMaxDynamicSharedMemorySize, SMEM_BYTES);
        cudaFuncSetAttribute((const void*)h_gemm<1, true, false>,
                             cudaFuncAttributeMaxDynamicSharedMemorySize, SMEM_BYTES);
        cudaFuncSetAttribute((const void*)h_gemm<2, true, false>,
                             cudaFuncAttributeMaxDynamicSharedMemorySize, SMEM_BYTES);
    }

    dim3 tb(32, 8);
    dim3 tg(D / 32, D / 32);

    // ---- fork weight prep onto s1 (no data deps)
    cudaEventRecord(evRoot, 0);
    cudaStreamWaitEvent(s1, evRoot, 0);
    k_transpose_h<<<tg, tb, 0, s1>>>(gcn_W, wtg_h);
    cudaEventRecord(evW1, s1);   // wtg ready (needed by GEMM1)
    for (int t = 0; t < 3; t++) {
        k_transpose_h<<<tg, tb, 0, s1>>>(rW1[t], wt1_h + (size_t)t * D * D);
        k_transpose_h<<<tg, tb, 0, s1>>>(rW2[t], wt2_h + (size_t)t * D * D);
    }
    k_cvt_h<<<H3 * D / 256, 256, 0, s1>>>(gru_whh, whh_h);
    cudaEventRecord(evW2, s1);   // all other weights ready

    // ---- main stream: gather, then fork the sim chain onto s2
    k_gather<<<NN * D / 256, 256>>>(h_con, h_dep, h_sem);
    cudaEventRecord(evG, 0);
    cudaStreamWaitEvent(s2, evG, 0);
    k_norm<<<S, 256, 0, s2>>>();
    k_sim<<<S, 256, 0, s2>>>();
    k_simnorm<<<1, 256, 0, s2>>>();
    cudaEventRecord(evSim, s2);

    // ---- GEMM1 (xw) overlaps with the sim chain
    cudaStreamWaitEvent(0, evW1, 0);
    h_gemm<2, true, true><<<dim3(D / BN, NN / BM), 256, SMEM_BYTES>>>(
        featsh, wtg_h, wtg_h, wtg_h, gcn_b, gcn_b, gcn_b,
        xh, xw, NN, D, D, NN);

    // ---- GCN aggregation (needs xw + sim)
    cudaStreamWaitEvent(0, evSim, 0);
    {
        dim3 g(S, D / 128);
        k_gcn_first<<<g, 128>>>(gcn_b);
    }

    // ---- GatedGraphConv: msg chain on s2 overlaps the gh GEMM on stream 0
    cudaStreamWaitEvent(0, evW2, 0);
    for (int l = 0; l < 2; l++) {
        cudaEventRecord(evX[l], 0);
        cudaStreamWaitEvent(s2, evX[l], 0);
        k_colsum<<<3, 256, 0, s2>>>();
        k_mvec<<<3, 256, 0, s2>>>(ggc_W + (size_t)l * D * D);
        k_gi<<<H3 / 8, 256, 0, s2>>>(gru_wih, gru_bih);
        cudaEventRecord(evGi[l], s2);

        h_gemm<1, true, false><<<dim3(H3 / BN, NN / BM), 256, SMEM_BYTES>>>(
            xh, whh_h, whh_h, whh_h, gru_bhh, gru_bhh, gru_bhh,
            ghh, nullptr, NN, H3, D, NN);

        cudaStreamWaitEvent(0, evGi[l], 0);
        if (l == 0) k_gru<false><<<NN * D / 512, 256>>>(gru_bih, h_feature);
        else        k_gru<true><<<NN * D / 512, 256>>>(gru_bih, h_feature);
    }

    // ---- three residual MLPs, monolithic (R12-proven), z stored fp16
    h_gemm<2, true, false><<<dim3(D / BN, NN / BM), 256, SMEM_BYTES>>>(
        featsh, wt1_h, wt1_h + (size_t)D * D, wt1_h + 2 * (size_t)D * D,
        rb1[0], rb1[1], rb1[2], xh, nullptr, NN, D, D, BSN);
    h_gemm<1, true, false><<<dim3(D / BN, NN / BM), 256, SMEM_BYTES>>>(
        xh, wt2_h, wt2_h + (size_t)D * D, wt2_h + 2 * (size_t)D * D,
        rb2[0], rb2[1], rb2[2], ghh, nullptr, NN, D, D, BSN);

    // ---- LayerNorm (fp16 z) -> d_out
    k_ln<<<NN, 256>>>(rg[0], rbeta[0], rg[1], rbeta[1], rg[2], rbeta[2], out);
}

// round 16
// speedup vs baseline: 1.1336x; 1.0454x over previous
#include <cuda_runtime.h>
#include <cuda_fp16.h>
#include <math.h>
#include <stdint.h>

// Problem constants
constexpr int D   = 768;
constexpr int S   = 128;
constexpr int BSN = 4096;    // B*S
constexpr int NN  = 12288;   // 3*B*S
constexpr int H3  = 2304;    // 3*D

// Scratch (device globals — allocation-free rule)
__device__ float  g_xw[S * D];            // raw xw for first 128 rows only
__device__ __half g_ghh[(size_t)NN * H3]; // GRU gh (fp16); reused as z fp16
__device__ float  g_feats32[S * D];
__device__ __half g_featsh[NN * D];       // feats fp16; reused as y fp16
__device__ __half g_xh[NN * D];           // x state fp16; reused as MLP hidden
__device__ __half g_whh_h[H3 * D];
__device__ __half g_wtg_h[D * D];
__device__ __half g_wt1_h[3 * D * D];
__device__ __half g_wt2_h[3 * D * D];
__device__ float  g_sim[S * S];
__device__ float  g_nrm[S];
__device__ float  g_dinv[S];
__device__ float  g_deginv[S];
__device__ float  g_svec[D];
__device__ float  g_mvec[D];
__device__ float  g_gi[H3];

// ============================ mma.sync helpers =============================
__device__ __forceinline__ uint32_t smem_u32(const void* p) {
    uint32_t a;
    asm("{ .reg .u64 t; cvta.to.shared.u64 t, %1; cvt.u32.u64 %0, t; }"
        : "=r"(a) : "l"(p));
    return a;
}
__device__ __forceinline__ void ldm_x4(uint32_t& r0, uint32_t& r1,
                                       uint32_t& r2, uint32_t& r3, uint32_t addr) {
    asm volatile("ldmatrix.sync.aligned.m8n8.x4.shared.b16 {%0,%1,%2,%3}, [%4];"
                 : "=r"(r0), "=r"(r1), "=r"(r2), "=r"(r3) : "r"(addr));
}
__device__ __forceinline__ void mma_f16(float* c, const uint32_t* a,
                                        const uint32_t* b) {
    asm volatile(
        "mma.sync.aligned.m16n8k16.row.col.f32.f16.f16.f32 "
        "{%0,%1,%2,%3}, {%4,%5,%6,%7}, {%8,%9}, {%0,%1,%2,%3};"
        : "+f"(c[0]), "+f"(c[1]), "+f"(c[2]), "+f"(c[3])
        : "r"(a[0]), "r"(a[1]), "r"(a[2]), "r"(a[3]), "r"(b[0]), "r"(b[1]));
}
__device__ __forceinline__ float sigm(float v) { return 1.f / (1.f + expf(-v)); }
#define CP16(dst, src) \
    asm volatile("cp.async.cg.shared.global [%0], [%1], 16;" :: "r"(dst), "l"(src))
#define CP_COMMIT() asm volatile("cp.async.commit_group;" ::: "memory")
#define CP_WAIT1()  asm volatile("cp.async.wait_group 1;" ::: "memory")

// ===========================================================================
// fp16 mma.sync GEMM (R12-proven): C[m,n] = sum_k A[m,k]*B[n,k]
// Block 128x256, BK=32, 8 warps (2m x 4n), warp tile 64x64, 3-stage cp.async.
// EPI: 0 none, 1 bias, 2 bias+relu. OUTH: fp16 output.
// GCN: bm==0 tile writes raw fp32 to Caux; others bias+relu fp16 to Cv.
// ===========================================================================
constexpr int BM = 128, BN = 256, BK = 32;
constexpr int ROWB2 = 80;
constexpr uint32_t A_BYTES = BM * ROWB2;              // 10240
constexpr uint32_t STAGE_BYTES = (BM + BN) * ROWB2;   // 30720
constexpr uint32_t SMEM_BYTES = 3 * STAGE_BYTES;      // 92160

template <int EPI, bool OUTH, bool GCN>
__global__ void __launch_bounds__(256, 1) h_gemm(
    const __half* __restrict__ A,
    const __half* __restrict__ B0, const __half* __restrict__ B1,
    const __half* __restrict__ B2,
    const float* __restrict__ bias0, const float* __restrict__ bias1,
    const float* __restrict__ bias2,
    void* __restrict__ Cv, float* __restrict__ Caux,
    int M, int N, int K, int rowSeg)
{
    extern __shared__ char smem[];
    const int bn = blockIdx.x * BN;
    const int bm = blockIdx.y * BM;
    const int seg = bm / rowSeg;
    const __half* Bp  = (seg == 0) ? B0 : ((seg == 1) ? B1 : B2);
    const float* bias = (seg == 0) ? bias0 : ((seg == 1) ? bias1 : bias2);

    const int tid  = threadIdx.x;
    const int lane = tid & 31;
    const int wid  = tid >> 5;
    const int wm   = (wid >> 2) * 64;
    const int wn   = (wid & 3) * 64;

    const uint32_t sS = smem_u32(smem);

    const int lr = tid >> 1;
    const int ko = (tid & 1) * 16;
    const __half* Agl = A  + (size_t)(bm + lr) * K + ko;
    const __half* Bgl = Bp + (size_t)(bn + lr) * K + ko;
    const uint32_t aDst = (uint32_t)lr * ROWB2 + ko * 2;
    const uint32_t bDst = A_BYTES + (uint32_t)lr * ROWB2 + ko * 2;

#define LOAD_STAGE(s, kb) do { \
    const int _k0 = (kb) * BK; \
    const uint32_t _base = sS + (uint32_t)(s) * STAGE_BYTES; \
    const __half* _a = Agl + _k0; \
    CP16(_base + aDst, _a); CP16(_base + aDst + 16, _a + 8); \
    const __half* _b = Bgl + _k0; \
    CP16(_base + bDst, _b); CP16(_base + bDst + 16, _b + 8); \
    _b += (size_t)128 * K; \
    CP16(_base + bDst + 128 * ROWB2, _b); \
    CP16(_base + bDst + 128 * ROWB2 + 16, _b + 8); \
} while (0)

    float c[4][8][4];
#pragma unroll
    for (int i = 0; i < 4; i++)
#pragma unroll
        for (int j = 0; j < 8; j++)
#pragma unroll
            for (int q = 0; q < 4; q++) c[i][j][q] = 0.f;

    LOAD_STAGE(0, 0); CP_COMMIT();
    LOAD_STAGE(1, 1); CP_COMMIT();

    const uint32_t aOff = (uint32_t)(wm + (lane & 15)) * ROWB2 + (lane >> 4) * 16;
    const uint32_t bOff = (uint32_t)(wn + (lane & 7) + ((lane >> 4) << 3)) * ROWB2
                          + ((lane >> 3) & 1) * 16;

    const int NS = K / BK;
    for (int ks = 0; ks < NS; ks++) {
        CP_WAIT1();
        __syncthreads();
        if (ks + 2 < NS) {
            LOAD_STAGE((ks + 2) % 3, ks + 2);
            CP_COMMIT();
        }
        const uint32_t aB = sS + (uint32_t)(ks % 3) * STAGE_BYTES;
        const uint32_t bB = aB + A_BYTES;
#pragma unroll
        for (int kh = 0; kh < 2; kh++) {
            uint32_t af[4][4], bf[8][2];
#pragma unroll
            for (int mt = 0; mt < 4; mt++)
                ldm_x4(af[mt][0], af[mt][1], af[mt][2], af[mt][3],
                       aB + aOff + kh * 32 + (uint32_t)mt * (16 * ROWB2));
#pragma unroll
            for (int jp = 0; jp < 4; jp++) {
                uint32_t r0, r1, r2, r3;
                ldm_x4(r0, r1, r2, r3,
                       bB + bOff + kh * 32 + (uint32_t)jp * (16 * ROWB2));
                bf[2 * jp][0] = r0;     bf[2 * jp][1] = r1;
                bf[2 * jp + 1][0] = r2; bf[2 * jp + 1][1] = r3;
            }
#pragma unroll
            for (int mt = 0; mt < 4; mt++)
#pragma unroll
                for (int nt = 0; nt < 8; nt++)
                    mma_f16(c[mt][nt], af[mt], bf[nt]);
        }
    }

    const int er = lane >> 2;
    const int ec = (lane & 3) * 2;
    const bool rawTile = GCN && (bm == 0);
#pragma unroll
    for (int mt = 0; mt < 4; mt++) {
        const int m = bm + wm + mt * 16 + er;
#pragma unroll
        for (int nt = 0; nt < 8; nt++) {
            const int n = bn + wn + nt * 8 + ec;
            float2 v0 = make_float2(c[mt][nt][0], c[mt][nt][1]);
            float2 v1 = make_float2(c[mt][nt][2], c[mt][nt][3]);
            if (rawTile) {
                *(float2*)(Caux + (size_t)m * N + n)       = v0;
                *(float2*)(Caux + (size_t)(m + 8) * N + n) = v1;
                continue;
            }
            if (EPI >= 1) {
                float b0 = bias[n], b1 = bias[n + 1];
                v0.x += b0; v0.y += b1;
                v1.x += b0; v1.y += b1;
            }
            if (EPI == 2) {
                v0.x = fmaxf(v0.x, 0.f); v0.y = fmaxf(v0.y, 0.f);
                v1.x = fmaxf(v1.x, 0.f); v1.y = fmaxf(v1.y, 0.f);
            }
            if (OUTH) {
                __half* Ch = (__half*)Cv;
                *(__half2*)(Ch + (size_t)m * N + n)       = __floats2half2_rn(v0.x, v0.y);
                *(__half2*)(Ch + (size_t)(m + 8) * N + n) = __floats2half2_rn(v1.x, v1.y);
            } else {
                float* Cf = (float*)Cv;
                *(float2*)(Cf + (size_t)m * N + n)       = v0;
                *(float2*)(Cf + (size_t)(m + 8) * N + n) = v1;
            }
        }
    }
#undef LOAD_STAGE
}

// ============================ small kernels ================================
__global__ void k_transpose_h(const float* __restrict__ src, __half* __restrict__ dst)
{
    __shared__ float t[32][33];
    int bx = blockIdx.x * 32, by = blockIdx.y * 32;
    int x = bx + threadIdx.x;
#pragma unroll
    for (int j = 0; j < 32; j += 8)
        t[threadIdx.y + j][threadIdx.x] = src[(size_t)(by + threadIdx.y + j) * D + x];
    __syncthreads();
    int ox = by + threadIdx.x;
#pragma unroll
    for (int j = 0; j < 32; j += 8)
        dst[(size_t)(bx + threadIdx.y + j) * D + ox] = __float2half(t[threadIdx.x][threadIdx.y + j]);
}

// float4 -> 2x half2 conversion (4 elems/thread)
__global__ void k_cvt_h(const float* __restrict__ src, __half* __restrict__ dst)
{
    int i = (blockIdx.x * 256 + threadIdx.x) * 4;
    float4 v = *(const float4*)(src + i);
    *(__half2*)(dst + i)     = __floats2half2_rn(v.x, v.y);
    *(__half2*)(dst + i + 2) = __floats2half2_rn(v.z, v.w);
}

// 2 elements per thread, half2 store
__global__ void k_gather(const float* __restrict__ a, const float* __restrict__ b,
                         const float* __restrict__ c)
{
    int o = (blockIdx.x * 256 + threadIdx.x) * 2;
    int n = o / D;
    int d = o - n * D;
    int base = n * (D / 3);
    int t0 = d % 3;
    const float* s0 = (t0 == 0) ? a : ((t0 == 1) ? b : c);
    int t1 = (d + 1) % 3;
    const float* s1 = (t1 == 0) ? a : ((t1 == 1) ? b : c);
    float v0 = s0[base + d / 3];
    float v1 = s1[base + (d + 1) / 3];
    *(__half2*)(g_featsh + o) = __floats2half2_rn(v0, v1);
    if (o < S * D) *(float2*)(g_feats32 + o) = make_float2(v0, v1);
}

__global__ void k_norm()
{
    int i = blockIdx.x;
    float s = 0.f;
    for (int k = threadIdx.x; k < D; k += 256) {
        float v = g_feats32[i * D + k];
        s = fmaf(v, v, s);
    }
    __shared__ float sh[256];
    sh[threadIdx.x] = s; __syncthreads();
    for (int t = 128; t > 0; t >>= 1) {
        if (threadIdx.x < t) sh[threadIdx.x] += sh[threadIdx.x + t];
        __syncthreads();
    }
    if (threadIdx.x == 0) g_nrm[i] = fmaxf(sqrtf(sh[0]), 1e-8f);
}

__global__ void k_sim()
{
    int i = blockIdx.x;
    __shared__ float fi[D];
    for (int k = threadIdx.x; k < D; k += 256) fi[k] = g_feats32[i * D + k];
    __syncthreads();
    int warp = threadIdx.x >> 5, lane = threadIdx.x & 31;
    float ni = g_nrm[i];
    for (int jj = 0; jj < 16; jj++) {
        int j = warp * 16 + jj;
        float s = 0.f;
        for (int k = lane; k < D; k += 32) s = fmaf(fi[k], g_feats32[j * D + k], s);
        for (int o = 16; o > 0; o >>= 1) s += __shfl_down_sync(0xffffffffu, s, o);
        if (lane == 0) g_sim[i * S + j] = s / (ni * g_nrm[j]);
    }
}

__global__ void k_simnorm()
{
    __shared__ float smn[256], smx[256];
    int tid = threadIdx.x;
    float mn = 1e30f, mx = -1e30f;
    for (int e = tid; e < S * S; e += 256) {
        float v = g_sim[e];
        mn = fminf(mn, v); mx = fmaxf(mx, v);
    }
    smn[tid] = mn; smx[tid] = mx;
    __syncthreads();
    for (int t = 128; t > 0; t >>= 1) {
        if (tid < t) {
            smn[tid] = fminf(smn[tid], smn[tid + t]);
            smx[tid] = fmaxf(smx[tid], smx[tid + t]);
        }
        __syncthreads();
    }
    float lo = smn[0];
    float inv = 1.f / (smx[0] - smn[0]);
    __syncthreads();
    for (int e = tid; e < S * S; e += 256) g_sim[e] = (g_sim[e] - lo) * inv;
    __syncthreads();
    if (tid < S) {
        float dg = 1.f;
        for (int i = 0; i < S; i++) dg += g_sim[i * S + tid];
        g_dinv[tid]   = rsqrtf(dg);
        g_deginv[tid] = 1.f / dg;
    }
}

__global__ void k_gcn_first(const float* __restrict__ gcn_b)
{
    int c = blockIdx.x;
    int d = blockIdx.y * 128 + threadIdx.x;
    __shared__ float col[S];
    col[threadIdx.x] = g_dinv[threadIdx.x] * g_sim[threadIdx.x * S + c];
    __syncthreads();
    float acc = 0.f;
#pragma unroll 8
    for (int i = 0; i < S; i++) acc = fmaf(col[i], g_xw[i * D + d], acc);
    float v = g_dinv[c] * acc + g_xw[c * D + d] * g_deginv[c] + gcn_b[d];
    g_xh[c * D + d] = __float2half(fmaxf(v, 0.f));
}

__global__ void k_colsum()
{
    int d = blockIdx.x * 256 + threadIdx.x;
    float s = 0.f;
    for (int r = 0; r < S; r++) s += __half2float(g_xh[r * D + d]);
    g_svec[d] = s;
}

__global__ void k_mvec(const float* __restrict__ W)
{
    int d = blockIdx.x * 256 + threadIdx.x;
    float acc = 0.f;
    for (int k = 0; k < D; k++) acc = fmaf(g_svec[k], W[k * D + d], acc);
    g_mvec[d] = acc;
}

__global__ void k_gi(const float* __restrict__ wih, const float* __restrict__ bih)
{
    int warp = threadIdx.x >> 5, lane = threadIdx.x & 31;
    int o = blockIdx.x * 8 + warp;
    float s = 0.f;
    for (int k = lane; k < D; k += 32) s = fmaf(g_mvec[k], wih[o * D + k], s);
    for (int off = 16; off > 0; off >>= 1) s += __shfl_down_sync(0xffffffffu, s, off);
    if (lane == 0) g_gi[o] = s + bih[o];
}

template <bool LAST>
__global__ void k_gru(const float* __restrict__ bih, const float* __restrict__ hfeat)
{
    int p = blockIdx.x * 256 + threadIdx.x;   // pair index
    int o = p * 2;
    int n = o / D;
    int d = o - n * D;
    float gir0, gir1, giz0, giz1, gin0, gin1;
    if (n < S) {
        gir0 = g_gi[d];        gir1 = g_gi[d + 1];
        giz0 = g_gi[D + d];    giz1 = g_gi[D + d + 1];
        gin0 = g_gi[2*D + d];  gin1 = g_gi[2*D + d + 1];
    } else {
        gir0 = bih[d];         gir1 = bih[d + 1];
        giz0 = bih[D + d];     giz1 = bih[D + d + 1];
        gin0 = bih[2*D + d];   gin1 = bih[2*D + d + 1];
    }
    const size_t gb = (size_t)n * H3;
    float2 hr = __half22float2(*(const __half2*)(g_ghh + gb + d));
    float2 hz = __half22float2(*(const __half2*)(g_ghh + gb + D + d));
    float2 hn = __half22float2(*(const __half2*)(g_ghh + gb + 2*D + d));
    float2 h  = __half22float2(*(const __half2*)(g_xh + o));
    float r0 = sigm(gir0 + hr.x), r1 = sigm(gir1 + hr.y);
    float z0 = sigm(giz0 + hz.x), z1 = sigm(giz1 + hz.y);
    float n0 = tanhf(gin0 + r0 * hn.x), n1 = tanhf(gin1 + r1 * hn.y);
    float o0 = (1.f - z0) * n0 + z0 * h.x;
    float o1 = (1.f - z1) * n1 + z1 * h.y;
    if (LAST) {
        int hb = o % (BSN * D);
        float2 hf = *(const float2*)(hfeat + hb);
        *(__half2*)(g_featsh + o) =
            __floats2half2_rn(hf.x + fmaxf(o0, 0.f), hf.y + fmaxf(o1, 0.f));
    } else {
        *(__half2*)(g_xh + o) = __floats2half2_rn(o0, o1);
    }
}

// LayerNorm reading fp16 z. 128 threads, half2 loads, warp-shuffle reduction.
__global__ void __launch_bounds__(128) k_ln(
    const float* __restrict__ g1, const float* __restrict__ be1,
    const float* __restrict__ g2, const float* __restrict__ be2,
    const float* __restrict__ g3, const float* __restrict__ be3,
    float* __restrict__ out)
{
    int r = blockIdx.x;
    int t = r / BSN;
    const float* gg = (t == 0) ? g1 : ((t == 1) ? g2 : g3);
    const float* bb = (t == 0) ? be1 : ((t == 1) ? be2 : be3);
    const __half* z = g_ghh + (size_t)r * D;
    const int tid = threadIdx.x;
    const int e0 = tid * 2;

    float2 v0 = __half22float2(*(const __half2*)(z + e0));
    float2 v1 = __half22float2(*(const __half2*)(z + e0 + 256));
    float2 v2 = __half22float2(*(const __half2*)(z + e0 + 512));

    __shared__ float sw[4];
    const int lane = tid & 31, warp = tid >> 5;

    float s = v0.x + v0.y + v1.x + v1.y + v2.x + v2.y;
#pragma unroll
    for (int off = 16; off > 0; off >>= 1) s += __shfl_down_sync(0xffffffffu, s, off);
    if (lane == 0) sw[warp] = s;
    __syncthreads();
    float mu = (sw[0] + sw[1] + sw[2] + sw[3]) * (1.f / 768.f);

    float d00 = v0.x - mu, d01 = v0.y - mu;
    float d10 = v1.x - mu, d11 = v1.y - mu;
    float d20 = v2.x - mu, d21 = v2.y - mu;
    float q = d00*d00 + d01*d01 + d10*d10 + d11*d11 + d20*d20 + d21*d21;
#pragma unroll
    for (int off = 16; off > 0; off >>= 1) q += __shfl_down_sync(0xffffffffu, q, off);
    __syncthreads();
    if (lane == 0) sw[warp] = q;
    __syncthreads();
    float rstd = rsqrtf((sw[0] + sw[1] + sw[2] + sw[3]) * (1.f / 768.f) + 1e-5f);

    float* o = out + (size_t)r * D;
    float2 gA = *(const float2*)(gg + e0);
    float2 bA = *(const float2*)(bb + e0);
    *(float2*)(o + e0) = make_float2(d00 * rstd * gA.x + bA.x,
                                     d01 * rstd * gA.y + bA.y);
    float2 gB = *(const float2*)(gg + e0 + 256);
    float2 bB = *(const float2*)(bb + e0 + 256);
    *(float2*)(o + e0 + 256) = make_float2(d10 * rstd * gB.x + bB.x,
                                           d11 * rstd * gB.y + bB.y);
    float2 gC = *(const float2*)(gg + e0 + 512);
    float2 bC = *(const float2*)(bb + e0 + 512);
    *(float2*)(o + e0 + 512) = make_float2(d20 * rstd * gC.x + bC.x,
                                           d21 * rstd * gC.y + bC.y);
}

// ---------------------------------------------------------------------------
extern "C" void kernel_launch(void* const* d_in, const int* in_sizes, int n_in,
                              void* d_out, int out_size)
{
    const float* h_feature = (const float*)d_in[0];
    const float* h_con     = (const float*)d_in[1];
    const float* h_dep     = (const float*)d_in[2];
    const float* h_sem     = (const float*)d_in[3];
    const float* gcn_W     = (const float*)d_in[4];
    const float* gcn_b     = (const float*)d_in[5];
    const float* ggc_W     = (const float*)d_in[6];
    const float* gru_wih   = (const float*)d_in[7];
    const float* gru_whh   = (const float*)d_in[8];
    const float* gru_bih   = (const float*)d_in[9];
    const float* gru_bhh   = (const float*)d_in[10];
    const float* rW1[3]   = {(const float*)d_in[11], (const float*)d_in[17], (const float*)d_in[23]};
    const float* rb1[3]   = {(const float*)d_in[12], (const float*)d_in[18], (const float*)d_in[24]};
    const float* rW2[3]   = {(const float*)d_in[13], (const float*)d_in[19], (const float*)d_in[25]};
    const float* rb2[3]   = {(const float*)d_in[14], (const float*)d_in[20], (const float*)d_in[26]};
    const float* rg[3]    = {(const float*)d_in[15], (const float*)d_in[21], (const float*)d_in[27]};
    const float* rbeta[3] = {(const float*)d_in[16], (const float*)d_in[22], (const float*)d_in[28]};
    float* out = (float*)d_out;

    float *xw;
    __half *ghh, *featsh, *xh, *whh_h, *wtg_h, *wt1_h, *wt2_h;
    cudaGetSymbolAddress((void**)&xw,     g_xw);
    cudaGetSymbolAddress((void**)&ghh,    g_ghh);
    cudaGetSymbolAddress((void**)&featsh, g_featsh);
    cudaGetSymbolAddress((void**)&xh,     g_xh);
    cudaGetSymbolAddress((void**)&whh_h,  g_whh_h);
    cudaGetSymbolAddress((void**)&wtg_h,  g_wtg_h);
    cudaGetSymbolAddress((void**)&wt1_h,  g_wt1_h);
    cudaGetSymbolAddress((void**)&wt2_h,  g_wt2_h);

    // One-time stream/event setup (runs during the un-captured correctness call)
    static cudaStream_t s1 = nullptr, s2 = nullptr;
    static cudaEvent_t evRoot, evW1, evW2, evG, evSim, evX[2], evGi[2];
    if (!s1) {
        cudaStreamCreateWithFlags(&s1, cudaStreamNonBlocking);
        cudaStreamCreateWithFlags(&s2, cudaStreamNonBlocking);
        cudaEventCreateWithFlags(&evRoot, cudaEventDisableTiming);
        cudaEventCreateWithFlags(&evW1,   cudaEventDisableTiming);
        cudaEventCreateWithFlags(&evW2,   cudaEventDisableTiming);
        cudaEventCreateWithFlags(&evG,    cudaEventDisableTiming);
        cudaEventCreateWithFlags(&evSim,  cudaEventDisableTiming);
        for (int i = 0; i < 2; i++) {
            cudaEventCreateWithFlags(&evX[i],  cudaEventDisableTiming);
            cudaEventCreateWithFlags(&evGi[i], cudaEventDisableTiming);
        }
        cudaFuncSetAttribute((const void*)h_gemm<2, true, true>,
                             cudaFuncAttributeMaxDynamicSharedMemorySize, SMEM_BYTES);
        cudaFuncSetAttribute((const void*)h_gemm<1, true, false>,
                             cudaFuncAttributeMaxDynamicSharedMemorySize, SMEM_BYTES);
        cudaFuncSetAttribute((const void*)h_gemm<2, true, false>,
                             cudaFuncAttributeMaxDynamicSharedMemorySize, SMEM_BYTES);
    }

    dim3 tb(32, 8);
    dim3 tg(D / 32, D / 32);

    // ---- fork weight prep onto s1 (no data deps)
    cudaEventRecord(evRoot, 0);
    cudaStreamWaitEvent(s1, evRoot, 0);
    k_transpose_h<<<tg, tb, 0, s1>>>(gcn_W, wtg_h);
    cudaEventRecord(evW1, s1);   // wtg ready (needed by GEMM1)
    for (int t = 0; t < 3; t++) {
        k_transpose_h<<<tg, tb, 0, s1>>>(rW1[t], wt1_h + (size_t)t * D * D);
        k_transpose_h<<<tg, tb, 0, s1>>>(rW2[t], wt2_h + (size_t)t * D * D);
    }
    k_cvt_h<<<H3 * D / 1024, 256, 0, s1>>>(gru_whh, whh_h);
    cudaEventRecord(evW2, s1);   // all other weights ready

    // ---- main stream: gather, then fork the sim chain onto s2
    k_gather<<<NN * D / 512, 256>>>(h_con, h_dep, h_sem);
    cudaEventRecord(evG, 0);
    cudaStreamWaitEvent(s2, evG, 0);
    k_norm<<<S, 256, 0, s2>>>();
    k_sim<<<S, 256, 0, s2>>>();
    k_simnorm<<<1, 256, 0, s2>>>();
    cudaEventRecord(evSim, s2);

    // ---- GEMM1 (xw) overlaps with the sim chain
    cudaStreamWaitEvent(0, evW1, 0);
    h_gemm<2, true, true><<<dim3(D / BN, NN / BM), 256, SMEM_BYTES>>>(
        featsh, wtg_h, wtg_h, wtg_h, gcn_b, gcn_b, gcn_b,
        xh, xw, NN, D, D, NN);

    // ---- GCN aggregation (needs xw + sim)
    cudaStreamWaitEvent(0, evSim, 0);
    {
        dim3 g(S, D / 128);
        k_gcn_first<<<g, 128>>>(gcn_b);
    }

    // ---- GatedGraphConv: msg chain on s2 overlaps the gh GEMM on stream 0
    cudaStreamWaitEvent(0, evW2, 0);
    for (int l = 0; l < 2; l++) {
        cudaEventRecord(evX[l], 0);
        cudaStreamWaitEvent(s2, evX[l], 0);
        k_colsum<<<3, 256, 0, s2>>>();
        k_mvec<<<3, 256, 0, s2>>>(ggc_W + (size_t)l * D * D);
        k_gi<<<H3 / 8, 256, 0, s2>>>(gru_wih, gru_bih);
        cudaEventRecord(evGi[l], s2);

        h_gemm<1, true, false><<<dim3(H3 / BN, NN / BM), 256, SMEM_BYTES>>>(
            xh, whh_h, whh_h, whh_h, gru_bhh, gru_bhh, gru_bhh,
            ghh, nullptr, NN, H3, D, NN);

        cudaStreamWaitEvent(0, evGi[l], 0);
        if (l == 0) k_gru<false><<<NN * D / 512, 256>>>(gru_bih, h_feature);
        else        k_gru<true><<<NN * D / 512, 256>>>(gru_bih, h_feature);
    }

    // ---- three residual MLPs, monolithic (R12-proven), z stored fp16
    h_gemm<2, true, false><<<dim3(D / BN, NN / BM), 256, SMEM_BYTES>>>(
        featsh, wt1_h, wt1_h + (size_t)D * D, wt1_h + 2 * (size_t)D * D,
        rb1[0], rb1[1], rb1[2], xh, nullptr, NN, D, D, BSN);
    h_gemm<1, true, false><<<dim3(D / BN, NN / BM), 256, SMEM_BYTES>>>(
        xh, wt2_h, wt2_h + (size_t)D * D, wt2_h + 2 * (size_t)D * D,
        rb2[0], rb2[1], rb2[2], ghh, nullptr, NN, D, D, BSN);

    // ---- LayerNorm (fp16 z, vectorized) -> d_out
    k_ln<<<NN, 128>>>(rg[0], rbeta[0], rg[1], rbeta[1], rg[2], rbeta[2], out);
}